// round 1
// baseline (speedup 1.0000x reference)
#include <cuda_runtime.h>
#include <math.h>

#define Bz 4
#define Sz 2048
#define Ez 1024
#define Hz 16
#define DKz 64

// Scratch (no allocs allowed): q/k/v projections and attention context,
// all stored [B,S,E] with E index = h*64 + d for attention convenience.
__device__ float g_q[Bz * Sz * Ez];
__device__ float g_k[Bz * Sz * Ez];
__device__ float g_v[Bz * Sz * Ez];
__device__ float g_ctx[Bz * Sz * Ez];

// ---------------------------------------------------------------------------
// GEMM: O[M,N] = X[M,K] * W[N,K]^T + bias[N]   (NT, fp32)
// BM=BN=128, BK=16, 256 threads, 8x8 per thread (split 4+4 vectors).
// ---------------------------------------------------------------------------
#define GBM 128
#define GBN 128
#define GBK 16
#define GLDA 132  // +4 pad to soften transpose-store conflicts

__global__ __launch_bounds__(256) void gemm_nt_bias(
    const float* __restrict__ X, const float* __restrict__ W,
    const float* __restrict__ bias, float* __restrict__ O,
    int M, int N, int K)
{
    __shared__ float As[GBK][GLDA];
    __shared__ float Bs[GBK][GLDA];

    const int tid = threadIdx.x;
    const int tx = tid & 15;        // 0..15 -> cols 4*tx and 64+4*tx
    const int ty = tid >> 4;        // 0..15 -> rows 4*ty and 64+4*ty
    const int m0 = blockIdx.y * GBM;
    const int n0 = blockIdx.x * GBN;

    float acc[8][8];
#pragma unroll
    for (int i = 0; i < 8; i++)
#pragma unroll
        for (int j = 0; j < 8; j++) acc[i][j] = 0.0f;

    const int lr = tid >> 2;        // 0..63
    const int lc = tid & 3;         // float4 group within 16-wide K slab

    for (int k0 = 0; k0 < K; k0 += GBK) {
#pragma unroll
        for (int rr = 0; rr < 2; rr++) {
            int r = lr + rr * 64;
            float4 va = *(const float4*)&X[(size_t)(m0 + r) * K + k0 + lc * 4];
            As[lc * 4 + 0][r] = va.x;
            As[lc * 4 + 1][r] = va.y;
            As[lc * 4 + 2][r] = va.z;
            As[lc * 4 + 3][r] = va.w;
            float4 vb = *(const float4*)&W[(size_t)(n0 + r) * K + k0 + lc * 4];
            Bs[lc * 4 + 0][r] = vb.x;
            Bs[lc * 4 + 1][r] = vb.y;
            Bs[lc * 4 + 2][r] = vb.z;
            Bs[lc * 4 + 3][r] = vb.w;
        }
        __syncthreads();

#pragma unroll
        for (int kk = 0; kk < GBK; kk++) {
            float a[8], b[8];
            *(float4*)&a[0] = *(const float4*)&As[kk][4 * ty];
            *(float4*)&a[4] = *(const float4*)&As[kk][64 + 4 * ty];
            *(float4*)&b[0] = *(const float4*)&Bs[kk][4 * tx];
            *(float4*)&b[4] = *(const float4*)&Bs[kk][64 + 4 * tx];
#pragma unroll
            for (int i = 0; i < 8; i++)
#pragma unroll
                for (int j = 0; j < 8; j++)
                    acc[i][j] += a[i] * b[j];
        }
        __syncthreads();
    }

    // epilogue: rows {4ty+i, 64+4ty+i}, cols {4tx+j, 64+4tx+j}
#pragma unroll
    for (int ri = 0; ri < 8; ri++) {
        int mrow = m0 + ((ri < 4) ? (4 * ty + ri) : (64 + 4 * ty + (ri - 4)));
#pragma unroll
        for (int half = 0; half < 2; half++) {
            int n = n0 + half * 64 + 4 * tx;
            float4 o;
            o.x = acc[ri][half * 4 + 0] + bias[n + 0];
            o.y = acc[ri][half * 4 + 1] + bias[n + 1];
            o.z = acc[ri][half * 4 + 2] + bias[n + 2];
            o.w = acc[ri][half * 4 + 3] + bias[n + 3];
            *(float4*)&O[(size_t)mrow * N + n] = o;
        }
    }
}

// ---------------------------------------------------------------------------
// Flash attention (fp32, online softmax): per (b,h), 64-row Q tiles iterating
// 64-row K/V tiles. K tile XOR-swizzled to keep QK^T smem loads ~2-way.
// Dynamic smem: Qs(16K) Ks(16K) Vs(16K) Ps(16K) = 64 KB.
// ---------------------------------------------------------------------------
__global__ __launch_bounds__(256) void flash_attn(
    const float* __restrict__ Qg, const float* __restrict__ Kg,
    const float* __restrict__ Vg, float* __restrict__ Og)
{
    extern __shared__ float fsm[];
    float* Qs = fsm;            // [64][64]
    float* Ks = fsm + 4096;     // [64][64] swizzled groups
    float* Vs = fsm + 8192;     // [64][64]
    float* Ps = fsm + 12288;    // [64][64]

    const int tid = threadIdx.x;
    const int tx = tid & 15;    // kv-col / out-dim group
    const int ty = tid >> 4;    // q-row group
    const int qt = blockIdx.x;
    const int h  = blockIdx.y;
    const int b  = blockIdx.z;
    const float scale = 0.125f; // 1/sqrt(64)

    const size_t base = (size_t)b * Sz * Ez + (size_t)h * DKz;
    const float* qb = Qg + base;
    const float* kb = Kg + base;
    const float* vb = Vg + base;

    // Load Q tile (pre-scaled)
#pragma unroll
    for (int it = 0; it < 4; it++) {
        int idx = tid + it * 256;
        int r = idx >> 4, g = idx & 15;
        float4 v = *(const float4*)&qb[(size_t)(qt * 64 + r) * Ez + g * 4];
        v.x *= scale; v.y *= scale; v.z *= scale; v.w *= scale;
        *(float4*)&Qs[r * 64 + g * 4] = v;
    }

    float m_i[4], l_i[4], acc[4][4];
#pragma unroll
    for (int i = 0; i < 4; i++) {
        m_i[i] = -INFINITY;
        l_i[i] = 0.0f;
#pragma unroll
        for (int j = 0; j < 4; j++) acc[i][j] = 0.0f;
    }

    for (int kt = 0; kt < Sz / 64; kt++) {
        __syncthreads();  // prior PV / P reads done; safe to overwrite tiles
        // Load K (swizzled) and V tiles
#pragma unroll
        for (int it = 0; it < 4; it++) {
            int idx = tid + it * 256;
            int r = idx >> 4, g = idx & 15;
            float4 kvv = *(const float4*)&kb[(size_t)(kt * 64 + r) * Ez + g * 4];
            *(float4*)&Ks[r * 64 + 4 * (g ^ ((r >> 2) & 7))] = kvv;
            float4 vvv = *(const float4*)&vb[(size_t)(kt * 64 + r) * Ez + g * 4];
            *(float4*)&Vs[r * 64 + g * 4] = vvv;
        }
        __syncthreads();

        // S = Q K^T  (4x4 microtile per thread; Q rows 4ty+i, K rows 4tx+j)
        float s[4][4];
#pragma unroll
        for (int i = 0; i < 4; i++)
#pragma unroll
            for (int j = 0; j < 4; j++) s[i][j] = 0.0f;

#pragma unroll
        for (int c = 0; c < 16; c++) {
            float4 q4[4], k4[4];
#pragma unroll
            for (int i = 0; i < 4; i++)
                q4[i] = *(const float4*)&Qs[(4 * ty + i) * 64 + 4 * c];
#pragma unroll
            for (int j = 0; j < 4; j++) {
                int r2 = 4 * tx + j;
                k4[j] = *(const float4*)&Ks[r2 * 64 + 4 * (c ^ (tx & 7))];
            }
#pragma unroll
            for (int i = 0; i < 4; i++)
#pragma unroll
                for (int j = 0; j < 4; j++)
                    s[i][j] += q4[i].x * k4[j].x + q4[i].y * k4[j].y
                             + q4[i].z * k4[j].z + q4[i].w * k4[j].w;
        }

        // Online softmax update (row stats shared across the 16 tx lanes)
#pragma unroll
        for (int i = 0; i < 4; i++) {
            float mx = fmaxf(fmaxf(s[i][0], s[i][1]), fmaxf(s[i][2], s[i][3]));
#pragma unroll
            for (int msk = 8; msk >= 1; msk >>= 1)
                mx = fmaxf(mx, __shfl_xor_sync(0xffffffffu, mx, msk));
            float mnew = fmaxf(m_i[i], mx);
            float corr = __expf(m_i[i] - mnew);
            float rsum = 0.0f;
#pragma unroll
            for (int j = 0; j < 4; j++) {
                s[i][j] = __expf(s[i][j] - mnew);
                rsum += s[i][j];
            }
#pragma unroll
            for (int msk = 8; msk >= 1; msk >>= 1)
                rsum += __shfl_xor_sync(0xffffffffu, rsum, msk);
            l_i[i] = l_i[i] * corr + rsum;
            m_i[i] = mnew;
#pragma unroll
            for (int j = 0; j < 4; j++) acc[i][j] *= corr;
            *(float4*)&Ps[(4 * ty + i) * 64 + 4 * tx] =
                make_float4(s[i][0], s[i][1], s[i][2], s[i][3]);
        }
        __syncthreads();

        // O += P V   (out cols 4tx+j)
#pragma unroll
        for (int c = 0; c < 16; c++) {
            float4 p4[4], v4[4];
#pragma unroll
            for (int i = 0; i < 4; i++)
                p4[i] = *(const float4*)&Ps[(4 * ty + i) * 64 + 4 * c];
#pragma unroll
            for (int u = 0; u < 4; u++)
                v4[u] = *(const float4*)&Vs[(4 * c + u) * 64 + 4 * tx];
#pragma unroll
            for (int i = 0; i < 4; i++) {
                acc[i][0] += p4[i].x * v4[0].x + p4[i].y * v4[1].x
                           + p4[i].z * v4[2].x + p4[i].w * v4[3].x;
                acc[i][1] += p4[i].x * v4[0].y + p4[i].y * v4[1].y
                           + p4[i].z * v4[2].y + p4[i].w * v4[3].y;
                acc[i][2] += p4[i].x * v4[0].z + p4[i].y * v4[1].z
                           + p4[i].z * v4[2].z + p4[i].w * v4[3].z;
                acc[i][3] += p4[i].x * v4[0].w + p4[i].y * v4[1].w
                           + p4[i].z * v4[2].w + p4[i].w * v4[3].w;
            }
        }
    }

    // Normalize and write ctx[b, s, h*64 + d]
#pragma unroll
    for (int i = 0; i < 4; i++) {
        float inv = 1.0f / l_i[i];
        float4 o = make_float4(acc[i][0] * inv, acc[i][1] * inv,
                               acc[i][2] * inv, acc[i][3] * inv);
        size_t row = (size_t)(b * Sz + qt * 64 + 4 * ty + i);
        *(float4*)&Og[row * Ez + h * 64 + 4 * tx] = o;
    }
}

// ---------------------------------------------------------------------------
extern "C" void kernel_launch(void* const* d_in, const int* in_sizes, int n_in,
                              void* d_out, int out_size)
{
    const float* Q  = (const float*)d_in[0];
    const float* K  = (const float*)d_in[1];
    const float* V  = (const float*)d_in[2];
    const float* Wq = (const float*)d_in[3];
    const float* bq = (const float*)d_in[4];
    const float* Wk = (const float*)d_in[5];
    const float* bk = (const float*)d_in[6];
    const float* Wv = (const float*)d_in[7];
    const float* bv = (const float*)d_in[8];
    const float* Wo = (const float*)d_in[9];
    const float* bo = (const float*)d_in[10];
    float* out = (float*)d_out;

    float *gq, *gk, *gv, *gctx;
    cudaGetSymbolAddress((void**)&gq,  g_q);
    cudaGetSymbolAddress((void**)&gk,  g_k);
    cudaGetSymbolAddress((void**)&gv,  g_v);
    cudaGetSymbolAddress((void**)&gctx, g_ctx);

    cudaFuncSetAttribute(flash_attn,
                         cudaFuncAttributeMaxDynamicSharedMemorySize, 65536);

    const int M = Bz * Sz;           // 8192
    dim3 ggrid(Ez / GBN, M / GBM);   // (8, 64)

    gemm_nt_bias<<<ggrid, 256>>>(Q, Wq, bq, gq, M, Ez, Ez);
    gemm_nt_bias<<<ggrid, 256>>>(K, Wk, bk, gk, M, Ez, Ez);
    gemm_nt_bias<<<ggrid, 256>>>(V, Wv, bv, gv, M, Ez, Ez);

    flash_attn<<<dim3(Sz / 64, Hz, Bz), 256, 65536>>>(gq, gk, gv, gctx);

    gemm_nt_bias<<<ggrid, 256>>>(gctx, Wo, bo, out, M, Ez, Ez);
}

// round 3
// speedup vs baseline: 1.3147x; 1.3147x over previous
#include <cuda_runtime.h>
#include <cuda_bf16.h>
#include <math.h>
#include <stdint.h>

#define Bz 4
#define Sz 2048
#define Ez 1024
#define Hz 16
#define DKz 64

// ---------------------------------------------------------------------------
// Scratch (no allocs allowed)
// ---------------------------------------------------------------------------
__device__ float g_q[Bz * Sz * Ez];
__device__ float g_k[Bz * Sz * Ez];
__device__ float g_v[Bz * Sz * Ez];
__device__ float g_ctx[Bz * Sz * Ez];
__device__ __nv_bfloat16 g_xhi[Bz * Sz * Ez];
__device__ __nv_bfloat16 g_xlo[Bz * Sz * Ez];
__device__ __nv_bfloat16 g_whi[Ez * Ez];
__device__ __nv_bfloat16 g_wlo[Ez * Ez];

// ---------------------------------------------------------------------------
// Base-target PTX helpers (NO tcgen05 — harness compiles for sm_103 base)
// ---------------------------------------------------------------------------
__device__ __forceinline__ uint32_t smem_u32(const void* p) {
    uint32_t a;
    asm("{ .reg .u64 t; cvta.to.shared.u64 t, %1; cvt.u32.u64 %0, t; }"
        : "=r"(a) : "l"(p));
    return a;
}
__device__ __forceinline__ void cp16(uint32_t dst, const void* src) {
    asm volatile("cp.async.cg.shared.global [%0], [%1], 16;" :: "r"(dst), "l"(src));
}
__device__ __forceinline__ void cp_commit() {
    asm volatile("cp.async.commit_group;" ::: "memory");
}
__device__ __forceinline__ void cp_wait0() {
    asm volatile("cp.async.wait_group 0;" ::: "memory");
}
__device__ __forceinline__ void cp_wait1() {
    asm volatile("cp.async.wait_group 1;" ::: "memory");
}
__device__ __forceinline__ void ldsm4(uint32_t& r0, uint32_t& r1, uint32_t& r2,
                                      uint32_t& r3, uint32_t addr) {
    asm volatile("ldmatrix.sync.aligned.m8n8.x4.shared.b16 {%0,%1,%2,%3}, [%4];"
                 : "=r"(r0), "=r"(r1), "=r"(r2), "=r"(r3) : "r"(addr));
}
__device__ __forceinline__ void ldsm2(uint32_t& r0, uint32_t& r1, uint32_t addr) {
    asm volatile("ldmatrix.sync.aligned.m8n8.x2.shared.b16 {%0,%1}, [%2];"
                 : "=r"(r0), "=r"(r1) : "r"(addr));
}
__device__ __forceinline__ void mma16816(float* d, const uint32_t* a,
                                         const uint32_t* b) {
    asm volatile(
        "mma.sync.aligned.m16n8k16.row.col.f32.bf16.bf16.f32 "
        "{%0,%1,%2,%3}, {%4,%5,%6,%7}, {%8,%9}, {%0,%1,%2,%3};"
        : "+f"(d[0]), "+f"(d[1]), "+f"(d[2]), "+f"(d[3])
        : "r"(a[0]), "r"(a[1]), "r"(a[2]), "r"(a[3]), "r"(b[0]), "r"(b[1]));
}

// ---------------------------------------------------------------------------
// fp32 -> bf16 hi/lo split (3-term GEMM split: hi*hi + hi*lo + lo*hi)
// ---------------------------------------------------------------------------
__global__ __launch_bounds__(256) void conv_split(
    const float* __restrict__ x, __nv_bfloat16* __restrict__ hi,
    __nv_bfloat16* __restrict__ lo, int n)
{
    int i = (blockIdx.x * 256 + threadIdx.x) * 4;
    if (i >= n) return;
    float4 v = *(const float4*)&x[i];
    __nv_bfloat16 h0 = __float2bfloat16(v.x);
    __nv_bfloat16 h1 = __float2bfloat16(v.y);
    __nv_bfloat16 h2 = __float2bfloat16(v.z);
    __nv_bfloat16 h3 = __float2bfloat16(v.w);
    __nv_bfloat16 l0 = __float2bfloat16(v.x - __bfloat162float(h0));
    __nv_bfloat16 l1 = __float2bfloat16(v.y - __bfloat162float(h1));
    __nv_bfloat16 l2 = __float2bfloat16(v.z - __bfloat162float(h2));
    __nv_bfloat16 l3 = __float2bfloat16(v.w - __bfloat162float(h3));
    ((__nv_bfloat162*)hi)[i / 2]     = __nv_bfloat162(h0, h1);
    ((__nv_bfloat162*)hi)[i / 2 + 1] = __nv_bfloat162(h2, h3);
    ((__nv_bfloat162*)lo)[i / 2]     = __nv_bfloat162(l0, l1);
    ((__nv_bfloat162*)lo)[i / 2 + 1] = __nv_bfloat162(l2, l3);
}

// ---------------------------------------------------------------------------
// HMMA GEMM: O[M,N] = X[M,K]*W[N,K]^T + bias, bf16 3-term split, fp32 accum.
// Tile 128x128x32. 8 warps (4M x 2N), warp tile 32x64.
// Smem: rows padded to 80B (stride 5 mod 8 -> conflict-free ldmatrix).
// Stage = Ahi|Alo|Bhi|Blo, 4 x 10240B = 40KB; double-buffered cp.async.
// ---------------------------------------------------------------------------
#define GBK 32
#define LDT 80                       // padded row stride in bytes
#define TILE_B 10240                 // 128 * 80
#define STAGE_B 40960

__global__ __launch_bounds__(256) void gemm_tc(
    const __nv_bfloat16* __restrict__ Ahi, const __nv_bfloat16* __restrict__ Alo,
    const __nv_bfloat16* __restrict__ Bhi, const __nv_bfloat16* __restrict__ Blo,
    const float* __restrict__ bias, float* __restrict__ O, int M, int N, int K)
{
    extern __shared__ __align__(128) char smem[];
    const int tid = threadIdx.x;
    const int wid = tid >> 5;
    const int lane = tid & 31;
    const int wm = (wid >> 1) * 32;   // warp M offset in tile
    const int wn = (wid & 1) * 64;    // warp N offset in tile
    const int m0 = blockIdx.y * 128;
    const int n0 = blockIdx.x * 128;

    const uint32_t sb = smem_u32(smem);

    // ldmatrix per-lane base offsets (within a tile)
    const uint32_t arow = (uint32_t)(wm + (lane & 15)) * LDT + (lane >> 4) * 16;
    const uint32_t brow = (uint32_t)(wn + (lane & 7)) * LDT + ((lane >> 3) & 1) * 16;

    float acc[2][8][4];
#pragma unroll
    for (int mt = 0; mt < 2; mt++)
#pragma unroll
        for (int nt = 0; nt < 8; nt++)
#pragma unroll
            for (int i = 0; i < 4; i++) acc[mt][nt][i] = 0.0f;

    const int NIT = K / GBK;

    auto load_stage = [&](int it, int s) {
        const uint32_t stb = sb + s * STAGE_B;
        const int k0 = it * GBK;
#pragma unroll
        for (int half = 0; half < 2; half++) {
            int c = tid + half * 256;          // 0..511
            int row = c >> 2, ch = c & 3;
            uint32_t so = (uint32_t)row * LDT + ch * 16;
            size_t ga = (size_t)(m0 + row) * K + k0 + ch * 8;
            size_t gb = (size_t)(n0 + row) * K + k0 + ch * 8;
            cp16(stb + so,              Ahi + ga);
            cp16(stb + TILE_B + so,     Alo + ga);
            cp16(stb + 2 * TILE_B + so, Bhi + gb);
            cp16(stb + 3 * TILE_B + so, Blo + gb);
        }
        cp_commit();
    };

    load_stage(0, 0);

#pragma unroll 1
    for (int it = 0; it < NIT; it++) {
        const int s = it & 1;
        const bool pf = (it + 1 < NIT);
        if (pf) load_stage(it + 1, s ^ 1);
        if (pf) cp_wait1(); else cp_wait0();
        __syncthreads();

        const uint32_t Ab = sb + s * STAGE_B;
        const uint32_t Bb = Ab + 2 * TILE_B;
#pragma unroll
        for (int ks = 0; ks < 2; ks++) {
            uint32_t ah[2][4], al[2][4];
#pragma unroll
            for (int mt = 0; mt < 2; mt++) {
                uint32_t ao = arow + (uint32_t)mt * (16 * LDT) + ks * 32;
                ldsm4(ah[mt][0], ah[mt][1], ah[mt][2], ah[mt][3], Ab + ao);
                ldsm4(al[mt][0], al[mt][1], al[mt][2], al[mt][3],
                      Ab + TILE_B + ao);
            }
#pragma unroll
            for (int nt = 0; nt < 8; nt++) {
                uint32_t bo = brow + (uint32_t)nt * (8 * LDT) + ks * 32;
                uint32_t bh[2], bl[2];
                ldsm2(bh[0], bh[1], Bb + bo);
                ldsm2(bl[0], bl[1], Bb + TILE_B + bo);
#pragma unroll
                for (int mt = 0; mt < 2; mt++) {
                    mma16816(acc[mt][nt], ah[mt], bh);
                    mma16816(acc[mt][nt], ah[mt], bl);
                    mma16816(acc[mt][nt], al[mt], bh);
                }
            }
        }
        __syncthreads();
    }

    // epilogue: fragment (mt,nt): rows m0+wm+mt*16+{lane/4, +8},
    //           cols n0+wn+nt*8+2*(lane%4)
    const int r0 = m0 + wm + (lane >> 2);
    const int c0 = n0 + wn + 2 * (lane & 3);
#pragma unroll
    for (int mt = 0; mt < 2; mt++) {
#pragma unroll
        for (int nt = 0; nt < 8; nt++) {
            int cc = c0 + nt * 8;
            float bx = __ldg(&bias[cc]);
            float by = __ldg(&bias[cc + 1]);
            int ra = r0 + mt * 16;
            float2 v0 = make_float2(acc[mt][nt][0] + bx, acc[mt][nt][1] + by);
            float2 v1 = make_float2(acc[mt][nt][2] + bx, acc[mt][nt][3] + by);
            *(float2*)&O[(size_t)ra * N + cc] = v0;
            *(float2*)&O[(size_t)(ra + 8) * N + cc] = v1;
        }
    }
}

// ---------------------------------------------------------------------------
// Flash attention (fp32, online softmax) — unchanged (proven correct).
// ---------------------------------------------------------------------------
__global__ __launch_bounds__(256) void flash_attn(
    const float* __restrict__ Qg, const float* __restrict__ Kg,
    const float* __restrict__ Vg, float* __restrict__ Og)
{
    extern __shared__ float fsm[];
    float* Qs = fsm;
    float* Ks = fsm + 4096;
    float* Vs = fsm + 8192;
    float* Ps = fsm + 12288;

    const int tid = threadIdx.x;
    const int tx = tid & 15;
    const int ty = tid >> 4;
    const int qt = blockIdx.x;
    const int h  = blockIdx.y;
    const int b  = blockIdx.z;
    const float scale = 0.125f;

    const size_t base = (size_t)b * Sz * Ez + (size_t)h * DKz;
    const float* qb = Qg + base;
    const float* kb = Kg + base;
    const float* vb = Vg + base;

#pragma unroll
    for (int it = 0; it < 4; it++) {
        int idx = tid + it * 256;
        int r = idx >> 4, g = idx & 15;
        float4 v = *(const float4*)&qb[(size_t)(qt * 64 + r) * Ez + g * 4];
        v.x *= scale; v.y *= scale; v.z *= scale; v.w *= scale;
        *(float4*)&Qs[r * 64 + g * 4] = v;
    }

    float m_i[4], l_i[4], acc[4][4];
#pragma unroll
    for (int i = 0; i < 4; i++) {
        m_i[i] = -INFINITY;
        l_i[i] = 0.0f;
#pragma unroll
        for (int j = 0; j < 4; j++) acc[i][j] = 0.0f;
    }

    for (int kt = 0; kt < Sz / 64; kt++) {
        __syncthreads();
#pragma unroll
        for (int it = 0; it < 4; it++) {
            int idx = tid + it * 256;
            int r = idx >> 4, g = idx & 15;
            float4 kvv = *(const float4*)&kb[(size_t)(kt * 64 + r) * Ez + g * 4];
            *(float4*)&Ks[r * 64 + 4 * (g ^ ((r >> 2) & 7))] = kvv;
            float4 vvv = *(const float4*)&vb[(size_t)(kt * 64 + r) * Ez + g * 4];
            *(float4*)&Vs[r * 64 + g * 4] = vvv;
        }
        __syncthreads();

        float s[4][4];
#pragma unroll
        for (int i = 0; i < 4; i++)
#pragma unroll
            for (int j = 0; j < 4; j++) s[i][j] = 0.0f;

#pragma unroll
        for (int c = 0; c < 16; c++) {
            float4 q4[4], k4[4];
#pragma unroll
            for (int i = 0; i < 4; i++)
                q4[i] = *(const float4*)&Qs[(4 * ty + i) * 64 + 4 * c];
#pragma unroll
            for (int j = 0; j < 4; j++) {
                int r2 = 4 * tx + j;
                k4[j] = *(const float4*)&Ks[r2 * 64 + 4 * (c ^ (tx & 7))];
            }
#pragma unroll
            for (int i = 0; i < 4; i++)
#pragma unroll
                for (int j = 0; j < 4; j++)
                    s[i][j] += q4[i].x * k4[j].x + q4[i].y * k4[j].y
                             + q4[i].z * k4[j].z + q4[i].w * k4[j].w;
        }

#pragma unroll
        for (int i = 0; i < 4; i++) {
            float mx = fmaxf(fmaxf(s[i][0], s[i][1]), fmaxf(s[i][2], s[i][3]));
#pragma unroll
            for (int msk = 8; msk >= 1; msk >>= 1)
                mx = fmaxf(mx, __shfl_xor_sync(0xffffffffu, mx, msk));
            float mnew = fmaxf(m_i[i], mx);
            float corr = __expf(m_i[i] - mnew);
            float rsum = 0.0f;
#pragma unroll
            for (int j = 0; j < 4; j++) {
                s[i][j] = __expf(s[i][j] - mnew);
                rsum += s[i][j];
            }
#pragma unroll
            for (int msk = 8; msk >= 1; msk >>= 1)
                rsum += __shfl_xor_sync(0xffffffffu, rsum, msk);
            l_i[i] = l_i[i] * corr + rsum;
            m_i[i] = mnew;
#pragma unroll
            for (int j = 0; j < 4; j++) acc[i][j] *= corr;
            *(float4*)&Ps[(4 * ty + i) * 64 + 4 * tx] =
                make_float4(s[i][0], s[i][1], s[i][2], s[i][3]);
        }
        __syncthreads();

#pragma unroll
        for (int c = 0; c < 16; c++) {
            float4 p4[4], v4[4];
#pragma unroll
            for (int i = 0; i < 4; i++)
                p4[i] = *(const float4*)&Ps[(4 * ty + i) * 64 + 4 * c];
#pragma unroll
            for (int u = 0; u < 4; u++)
                v4[u] = *(const float4*)&Vs[(4 * c + u) * 64 + 4 * tx];
#pragma unroll
            for (int i = 0; i < 4; i++) {
                acc[i][0] += p4[i].x * v4[0].x + p4[i].y * v4[1].x
                           + p4[i].z * v4[2].x + p4[i].w * v4[3].x;
                acc[i][1] += p4[i].x * v4[0].y + p4[i].y * v4[1].y
                           + p4[i].z * v4[2].y + p4[i].w * v4[3].y;
                acc[i][2] += p4[i].x * v4[0].z + p4[i].y * v4[1].z
                           + p4[i].z * v4[2].z + p4[i].w * v4[3].z;
                acc[i][3] += p4[i].x * v4[0].w + p4[i].y * v4[1].w
                           + p4[i].z * v4[2].w + p4[i].w * v4[3].w;
            }
        }
    }

#pragma unroll
    for (int i = 0; i < 4; i++) {
        float inv = 1.0f / l_i[i];
        float4 o = make_float4(acc[i][0] * inv, acc[i][1] * inv,
                               acc[i][2] * inv, acc[i][3] * inv);
        size_t row = (size_t)(b * Sz + qt * 64 + 4 * ty + i);
        *(float4*)&Og[row * Ez + h * 64 + 4 * tx] = o;
    }
}

// ---------------------------------------------------------------------------
extern "C" void kernel_launch(void* const* d_in, const int* in_sizes, int n_in,
                              void* d_out, int out_size)
{
    const float* Q  = (const float*)d_in[0];
    const float* K  = (const float*)d_in[1];
    const float* V  = (const float*)d_in[2];
    const float* Wq = (const float*)d_in[3];
    const float* bq = (const float*)d_in[4];
    const float* Wk = (const float*)d_in[5];
    const float* bk = (const float*)d_in[6];
    const float* Wv = (const float*)d_in[7];
    const float* bv = (const float*)d_in[8];
    const float* Wo = (const float*)d_in[9];
    const float* bo = (const float*)d_in[10];
    float* out = (float*)d_out;

    float *gq, *gk, *gv, *gctx;
    __nv_bfloat16 *xhi, *xlo, *whi, *wlo;
    cudaGetSymbolAddress((void**)&gq,   g_q);
    cudaGetSymbolAddress((void**)&gk,   g_k);
    cudaGetSymbolAddress((void**)&gv,   g_v);
    cudaGetSymbolAddress((void**)&gctx, g_ctx);
    cudaGetSymbolAddress((void**)&xhi,  g_xhi);
    cudaGetSymbolAddress((void**)&xlo,  g_xlo);
    cudaGetSymbolAddress((void**)&whi,  g_whi);
    cudaGetSymbolAddress((void**)&wlo,  g_wlo);

    cudaFuncSetAttribute(flash_attn,
                         cudaFuncAttributeMaxDynamicSharedMemorySize, 65536);
    cudaFuncSetAttribute(gemm_tc,
                         cudaFuncAttributeMaxDynamicSharedMemorySize, 2 * STAGE_B);

    const int M = Bz * Sz;          // 8192
    const int NX = M * Ez;
    const int NW = Ez * Ez;
    dim3 ggrid(Ez / 128, M / 128);  // (8, 64)

    conv_split<<<NX / 1024, 256>>>(Q, xhi, xlo, NX);
    conv_split<<<NW / 1024, 256>>>(Wq, whi, wlo, NW);
    gemm_tc<<<ggrid, 256, 2 * STAGE_B>>>(xhi, xlo, whi, wlo, bq, gq, M, Ez, Ez);

    conv_split<<<NX / 1024, 256>>>(K, xhi, xlo, NX);
    conv_split<<<NW / 1024, 256>>>(Wk, whi, wlo, NW);
    gemm_tc<<<ggrid, 256, 2 * STAGE_B>>>(xhi, xlo, whi, wlo, bk, gk, M, Ez, Ez);

    conv_split<<<NX / 1024, 256>>>(V, xhi, xlo, NX);
    conv_split<<<NW / 1024, 256>>>(Wv, whi, wlo, NW);
    gemm_tc<<<ggrid, 256, 2 * STAGE_B>>>(xhi, xlo, whi, wlo, bv, gv, M, Ez, Ez);

    flash_attn<<<dim3(Sz / 64, Hz, Bz), 256, 65536>>>(gq, gk, gv, gctx);

    conv_split<<<NX / 1024, 256>>>(gctx, xhi, xlo, NX);
    conv_split<<<NW / 1024, 256>>>(Wo, whi, wlo, NW);
    gemm_tc<<<ggrid, 256, 2 * STAGE_B>>>(xhi, xlo, whi, wlo, bo, out, M, Ez, Ez);
}

// round 4
// speedup vs baseline: 3.5048x; 2.6659x over previous
#include <cuda_runtime.h>
#include <cuda_bf16.h>
#include <cuda_fp16.h>
#include <math.h>
#include <stdint.h>

#define Bz 4
#define Sz 2048
#define Ez 1024
#define Hz 16
#define DKz 64

// ---------------------------------------------------------------------------
// Scratch (no allocs allowed)
// ---------------------------------------------------------------------------
__device__ __half g_qh[Bz * Sz * Ez];
__device__ __half g_kh[Bz * Sz * Ez];
__device__ __half g_vh[Bz * Sz * Ez];
__device__ float g_ctx[Bz * Sz * Ez];
__device__ __nv_bfloat16 g_xhi[Bz * Sz * Ez];
__device__ __nv_bfloat16 g_xlo[Bz * Sz * Ez];
__device__ __nv_bfloat16 g_whi[Ez * Ez];
__device__ __nv_bfloat16 g_wlo[Ez * Ez];

// ---------------------------------------------------------------------------
// Base-target PTX helpers (NO tcgen05 — harness compiles for sm_103 base)
// ---------------------------------------------------------------------------
__device__ __forceinline__ uint32_t smem_u32(const void* p) {
    uint32_t a;
    asm("{ .reg .u64 t; cvta.to.shared.u64 t, %1; cvt.u32.u64 %0, t; }"
        : "=r"(a) : "l"(p));
    return a;
}
__device__ __forceinline__ void cp16(uint32_t dst, const void* src) {
    asm volatile("cp.async.cg.shared.global [%0], [%1], 16;" :: "r"(dst), "l"(src));
}
__device__ __forceinline__ void cp_commit() {
    asm volatile("cp.async.commit_group;" ::: "memory");
}
__device__ __forceinline__ void cp_wait0() {
    asm volatile("cp.async.wait_group 0;" ::: "memory");
}
__device__ __forceinline__ void cp_wait1() {
    asm volatile("cp.async.wait_group 1;" ::: "memory");
}
__device__ __forceinline__ void ldsm4(uint32_t& r0, uint32_t& r1, uint32_t& r2,
                                      uint32_t& r3, uint32_t addr) {
    asm volatile("ldmatrix.sync.aligned.m8n8.x4.shared.b16 {%0,%1,%2,%3}, [%4];"
                 : "=r"(r0), "=r"(r1), "=r"(r2), "=r"(r3) : "r"(addr));
}
__device__ __forceinline__ void ldsm2(uint32_t& r0, uint32_t& r1, uint32_t addr) {
    asm volatile("ldmatrix.sync.aligned.m8n8.x2.shared.b16 {%0,%1}, [%2];"
                 : "=r"(r0), "=r"(r1) : "r"(addr));
}
__device__ __forceinline__ void ldsm2t(uint32_t& r0, uint32_t& r1, uint32_t addr) {
    asm volatile("ldmatrix.sync.aligned.m8n8.x2.trans.shared.b16 {%0,%1}, [%2];"
                 : "=r"(r0), "=r"(r1) : "r"(addr));
}
__device__ __forceinline__ void mma_bf(float* d, const uint32_t* a,
                                       const uint32_t* b) {
    asm volatile(
        "mma.sync.aligned.m16n8k16.row.col.f32.bf16.bf16.f32 "
        "{%0,%1,%2,%3}, {%4,%5,%6,%7}, {%8,%9}, {%0,%1,%2,%3};"
        : "+f"(d[0]), "+f"(d[1]), "+f"(d[2]), "+f"(d[3])
        : "r"(a[0]), "r"(a[1]), "r"(a[2]), "r"(a[3]), "r"(b[0]), "r"(b[1]));
}
__device__ __forceinline__ void mma_fp(float* d, const uint32_t* a,
                                       const uint32_t* b) {
    asm volatile(
        "mma.sync.aligned.m16n8k16.row.col.f32.f16.f16.f32 "
        "{%0,%1,%2,%3}, {%4,%5,%6,%7}, {%8,%9}, {%0,%1,%2,%3};"
        : "+f"(d[0]), "+f"(d[1]), "+f"(d[2]), "+f"(d[3])
        : "r"(a[0]), "r"(a[1]), "r"(a[2]), "r"(a[3]), "r"(b[0]), "r"(b[1]));
}

// ---------------------------------------------------------------------------
// fp32 -> bf16 hi/lo split
// ---------------------------------------------------------------------------
__global__ __launch_bounds__(256) void conv_split(
    const float* __restrict__ x, __nv_bfloat16* __restrict__ hi,
    __nv_bfloat16* __restrict__ lo, int n)
{
    int i = (blockIdx.x * 256 + threadIdx.x) * 4;
    if (i >= n) return;
    float4 v = *(const float4*)&x[i];
    __nv_bfloat16 h0 = __float2bfloat16(v.x);
    __nv_bfloat16 h1 = __float2bfloat16(v.y);
    __nv_bfloat16 h2 = __float2bfloat16(v.z);
    __nv_bfloat16 h3 = __float2bfloat16(v.w);
    __nv_bfloat16 l0 = __float2bfloat16(v.x - __bfloat162float(h0));
    __nv_bfloat16 l1 = __float2bfloat16(v.y - __bfloat162float(h1));
    __nv_bfloat16 l2 = __float2bfloat16(v.z - __bfloat162float(h2));
    __nv_bfloat16 l3 = __float2bfloat16(v.w - __bfloat162float(h3));
    ((__nv_bfloat162*)hi)[i / 2]     = __nv_bfloat162(h0, h1);
    ((__nv_bfloat162*)hi)[i / 2 + 1] = __nv_bfloat162(h2, h3);
    ((__nv_bfloat162*)lo)[i / 2]     = __nv_bfloat162(l0, l1);
    ((__nv_bfloat162*)lo)[i / 2 + 1] = __nv_bfloat162(l2, l3);
}

// ---------------------------------------------------------------------------
// HMMA GEMM: O = X W^T + bias, bf16 3-term split, fp32 accum.
// HOUT=1 -> write __half output (for q/k/v); HOUT=0 -> fp32.
// ---------------------------------------------------------------------------
#define GBK 32
#define LDT 80
#define TILE_B 10240
#define STAGE_B 40960

template <int HOUT>
__global__ __launch_bounds__(256) void gemm_tc(
    const __nv_bfloat16* __restrict__ Ahi, const __nv_bfloat16* __restrict__ Alo,
    const __nv_bfloat16* __restrict__ Bhi, const __nv_bfloat16* __restrict__ Blo,
    const float* __restrict__ bias, void* __restrict__ Ov, int M, int N, int K)
{
    extern __shared__ __align__(128) char smem[];
    const int tid = threadIdx.x;
    const int wid = tid >> 5;
    const int lane = tid & 31;
    const int wm = (wid >> 1) * 32;
    const int wn = (wid & 1) * 64;
    const int m0 = blockIdx.y * 128;
    const int n0 = blockIdx.x * 128;

    const uint32_t sb = smem_u32(smem);
    const uint32_t arow = (uint32_t)(wm + (lane & 15)) * LDT + (lane >> 4) * 16;
    const uint32_t brow = (uint32_t)(wn + (lane & 7)) * LDT + ((lane >> 3) & 1) * 16;

    float acc[2][8][4];
#pragma unroll
    for (int mt = 0; mt < 2; mt++)
#pragma unroll
        for (int nt = 0; nt < 8; nt++)
#pragma unroll
            for (int i = 0; i < 4; i++) acc[mt][nt][i] = 0.0f;

    const int NIT = K / GBK;

    auto load_stage = [&](int it, int s) {
        const uint32_t stb = sb + s * STAGE_B;
        const int k0 = it * GBK;
#pragma unroll
        for (int half = 0; half < 2; half++) {
            int c = tid + half * 256;
            int row = c >> 2, ch = c & 3;
            uint32_t so = (uint32_t)row * LDT + ch * 16;
            size_t ga = (size_t)(m0 + row) * K + k0 + ch * 8;
            size_t gb = (size_t)(n0 + row) * K + k0 + ch * 8;
            cp16(stb + so,              Ahi + ga);
            cp16(stb + TILE_B + so,     Alo + ga);
            cp16(stb + 2 * TILE_B + so, Bhi + gb);
            cp16(stb + 3 * TILE_B + so, Blo + gb);
        }
        cp_commit();
    };

    load_stage(0, 0);

#pragma unroll 1
    for (int it = 0; it < NIT; it++) {
        const int s = it & 1;
        const bool pf = (it + 1 < NIT);
        if (pf) load_stage(it + 1, s ^ 1);
        if (pf) cp_wait1(); else cp_wait0();
        __syncthreads();

        const uint32_t Ab = sb + s * STAGE_B;
        const uint32_t Bb = Ab + 2 * TILE_B;
#pragma unroll
        for (int ks = 0; ks < 2; ks++) {
            uint32_t ah[2][4], al[2][4];
#pragma unroll
            for (int mt = 0; mt < 2; mt++) {
                uint32_t ao = arow + (uint32_t)mt * (16 * LDT) + ks * 32;
                ldsm4(ah[mt][0], ah[mt][1], ah[mt][2], ah[mt][3], Ab + ao);
                ldsm4(al[mt][0], al[mt][1], al[mt][2], al[mt][3],
                      Ab + TILE_B + ao);
            }
#pragma unroll
            for (int nt = 0; nt < 8; nt++) {
                uint32_t bo = brow + (uint32_t)nt * (8 * LDT) + ks * 32;
                uint32_t bh[2], bl[2];
                ldsm2(bh[0], bh[1], Bb + bo);
                ldsm2(bl[0], bl[1], Bb + TILE_B + bo);
#pragma unroll
                for (int mt = 0; mt < 2; mt++) {
                    mma_bf(acc[mt][nt], ah[mt], bh);
                    mma_bf(acc[mt][nt], ah[mt], bl);
                    mma_bf(acc[mt][nt], al[mt], bh);
                }
            }
        }
        __syncthreads();
    }

    const int r0 = m0 + wm + (lane >> 2);
    const int c0 = n0 + wn + 2 * (lane & 3);
#pragma unroll
    for (int mt = 0; mt < 2; mt++) {
#pragma unroll
        for (int nt = 0; nt < 8; nt++) {
            int cc = c0 + nt * 8;
            float bx = __ldg(&bias[cc]);
            float by = __ldg(&bias[cc + 1]);
            int ra = r0 + mt * 16;
            if (HOUT) {
                __half2* O = (__half2*)Ov;
                O[((size_t)ra * N + cc) / 2] =
                    __floats2half2_rn(acc[mt][nt][0] + bx, acc[mt][nt][1] + by);
                O[((size_t)(ra + 8) * N + cc) / 2] =
                    __floats2half2_rn(acc[mt][nt][2] + bx, acc[mt][nt][3] + by);
            } else {
                float* O = (float*)Ov;
                *(float2*)&O[(size_t)ra * N + cc] =
                    make_float2(acc[mt][nt][0] + bx, acc[mt][nt][1] + by);
                *(float2*)&O[(size_t)(ra + 8) * N + cc] =
                    make_float2(acc[mt][nt][2] + bx, acc[mt][nt][3] + by);
            }
        }
    }
}

// ---------------------------------------------------------------------------
// Flash attention, fp16 HMMA, fp32 online softmax.
// CTA: 128 Q rows x one (b,h); 8 warps x 16 rows. K/V tiles 64 keys,
// cp.async double-buffered. Rows padded to 144B (9*16B -> conflict-free ldsm).
// Smem: Q 18432 + 2 stages x (K 9216 + V 9216) = 55296 B.
// ---------------------------------------------------------------------------
#define LDH 144
#define QS_B (128 * LDH)
#define KV_B (64 * LDH)

__global__ __launch_bounds__(256) void flash_attn_h(
    const __half* __restrict__ Qg, const __half* __restrict__ Kg,
    const __half* __restrict__ Vg, float* __restrict__ Og)
{
    extern __shared__ __align__(128) char smem[];
    const int tid = threadIdx.x;
    const int wid = tid >> 5;
    const int lane = tid & 31;
    const int qt = blockIdx.x;
    const int h  = blockIdx.y;
    const int b  = blockIdx.z;

    const uint32_t sb = smem_u32(smem);
    const size_t hb = (size_t)b * Sz * Ez + (size_t)h * DKz;
    const __half* qg = Qg + hb + (size_t)qt * 128 * Ez;
    const __half* kg = Kg + hb;
    const __half* vg = Vg + hb;

    // Q tile load: 128 rows x 128B
#pragma unroll
    for (int i = 0; i < 4; i++) {
        int c = tid + i * 256;
        int row = c >> 3, ch = c & 7;
        cp16(sb + row * LDH + ch * 16, qg + (size_t)row * Ez + ch * 8);
    }
    cp_commit();

    auto load_kv = [&](int kt, int s) {
        const uint32_t kb = sb + QS_B + s * 2 * KV_B;
        const __half* kp = kg + (size_t)(kt * 64) * Ez;
        const __half* vp = vg + (size_t)(kt * 64) * Ez;
#pragma unroll
        for (int i = 0; i < 4; i++) {
            int c = tid + i * 256;
            int row = c >> 3, ch = c & 7;
            if (row < 64)
                cp16(kb + row * LDH + ch * 16, kp + (size_t)row * Ez + ch * 8);
            else
                cp16(kb + KV_B + (row - 64) * LDH + ch * 16,
                     vp + (size_t)(row - 64) * Ez + ch * 8);
        }
        cp_commit();
    };

    load_kv(0, 0);

    // per-lane ldmatrix bases
    const uint32_t arow = (uint32_t)(wid * 16 + (lane & 15)) * LDH +
                          (lane >> 4) * 16;
    const uint32_t brow = (uint32_t)(lane & 7) * LDH + ((lane >> 3) & 1) * 16;
    const uint32_t vrow = (uint32_t)(lane & 15) * LDH;

    float o[8][4];
#pragma unroll
    for (int nt = 0; nt < 8; nt++)
#pragma unroll
        for (int i = 0; i < 4; i++) o[nt][i] = 0.0f;
    float m0 = -INFINITY, m1 = -INFINITY, l0 = 0.0f, l1 = 0.0f;

    const int NT = Sz / 64;  // 32
#pragma unroll 1
    for (int it = 0; it < NT; it++) {
        const int s = it & 1;
        const bool pf = (it + 1 < NT);
        if (pf) load_kv(it + 1, s ^ 1);
        if (pf) cp_wait1(); else cp_wait0();
        __syncthreads();

        const uint32_t Kb = sb + QS_B + s * 2 * KV_B;
        const uint32_t Vb = Kb + KV_B;

        // S = Q K^T
        float sv[8][4];
#pragma unroll
        for (int nt = 0; nt < 8; nt++)
#pragma unroll
            for (int i = 0; i < 4; i++) sv[nt][i] = 0.0f;
#pragma unroll
        for (int ks = 0; ks < 4; ks++) {
            uint32_t qa[4];
            ldsm4(qa[0], qa[1], qa[2], qa[3], sb + arow + ks * 32);
#pragma unroll
            for (int nt = 0; nt < 8; nt++) {
                uint32_t kb2[2];
                ldsm2(kb2[0], kb2[1], Kb + brow + nt * (8 * LDH) + ks * 32);
                mma_fp(sv[nt], qa, kb2);
            }
        }

        // scale + online softmax (rows r=lane>>2 and r+8)
        float mx0 = -INFINITY, mx1 = -INFINITY;
#pragma unroll
        for (int nt = 0; nt < 8; nt++) {
            sv[nt][0] *= 0.125f; sv[nt][1] *= 0.125f;
            sv[nt][2] *= 0.125f; sv[nt][3] *= 0.125f;
            mx0 = fmaxf(mx0, fmaxf(sv[nt][0], sv[nt][1]));
            mx1 = fmaxf(mx1, fmaxf(sv[nt][2], sv[nt][3]));
        }
        mx0 = fmaxf(mx0, __shfl_xor_sync(0xffffffffu, mx0, 1));
        mx0 = fmaxf(mx0, __shfl_xor_sync(0xffffffffu, mx0, 2));
        mx1 = fmaxf(mx1, __shfl_xor_sync(0xffffffffu, mx1, 1));
        mx1 = fmaxf(mx1, __shfl_xor_sync(0xffffffffu, mx1, 2));
        float mn0 = fmaxf(m0, mx0), mn1 = fmaxf(m1, mx1);
        float cr0 = __expf(m0 - mn0), cr1 = __expf(m1 - mn1);
        float sum0 = 0.0f, sum1 = 0.0f;
#pragma unroll
        for (int nt = 0; nt < 8; nt++) {
            sv[nt][0] = __expf(sv[nt][0] - mn0);
            sv[nt][1] = __expf(sv[nt][1] - mn0);
            sv[nt][2] = __expf(sv[nt][2] - mn1);
            sv[nt][3] = __expf(sv[nt][3] - mn1);
            sum0 += sv[nt][0] + sv[nt][1];
            sum1 += sv[nt][2] + sv[nt][3];
        }
        sum0 += __shfl_xor_sync(0xffffffffu, sum0, 1);
        sum0 += __shfl_xor_sync(0xffffffffu, sum0, 2);
        sum1 += __shfl_xor_sync(0xffffffffu, sum1, 1);
        sum1 += __shfl_xor_sync(0xffffffffu, sum1, 2);
        l0 = l0 * cr0 + sum0;
        l1 = l1 * cr1 + sum1;
        m0 = mn0; m1 = mn1;
#pragma unroll
        for (int nt = 0; nt < 8; nt++) {
            o[nt][0] *= cr0; o[nt][1] *= cr0;
            o[nt][2] *= cr1; o[nt][3] *= cr1;
        }

        // O += P V  (P from sv registers; V via ldmatrix.trans)
#pragma unroll
        for (int ks = 0; ks < 4; ks++) {
            uint32_t pa[4];
            __half2 h0h = __floats2half2_rn(sv[2 * ks][0], sv[2 * ks][1]);
            __half2 h1h = __floats2half2_rn(sv[2 * ks][2], sv[2 * ks][3]);
            __half2 h2h = __floats2half2_rn(sv[2 * ks + 1][0], sv[2 * ks + 1][1]);
            __half2 h3h = __floats2half2_rn(sv[2 * ks + 1][2], sv[2 * ks + 1][3]);
            pa[0] = *(uint32_t*)&h0h; pa[1] = *(uint32_t*)&h1h;
            pa[2] = *(uint32_t*)&h2h; pa[3] = *(uint32_t*)&h3h;
#pragma unroll
            for (int nt = 0; nt < 8; nt++) {
                uint32_t vb2[2];
                ldsm2t(vb2[0], vb2[1], Vb + vrow + ks * (16 * LDH) + nt * 16);
                mma_fp(o[nt], pa, vb2);
            }
        }
        __syncthreads();
    }

    // write ctx[b, s, h*64+dk]
    const float i0 = 1.0f / l0, i1 = 1.0f / l1;
    const int gr0 = qt * 128 + wid * 16 + (lane >> 2);
    const int cbase = h * 64 + 2 * (lane & 3);
#pragma unroll
    for (int nt = 0; nt < 8; nt++) {
        int cc = cbase + nt * 8;
        *(float2*)&Og[((size_t)(b * Sz + gr0)) * Ez + cc] =
            make_float2(o[nt][0] * i0, o[nt][1] * i0);
        *(float2*)&Og[((size_t)(b * Sz + gr0 + 8)) * Ez + cc] =
            make_float2(o[nt][2] * i1, o[nt][3] * i1);
    }
}

// ---------------------------------------------------------------------------
extern "C" void kernel_launch(void* const* d_in, const int* in_sizes, int n_in,
                              void* d_out, int out_size)
{
    const float* Q  = (const float*)d_in[0];
    const float* K  = (const float*)d_in[1];
    const float* V  = (const float*)d_in[2];
    const float* Wq = (const float*)d_in[3];
    const float* bq = (const float*)d_in[4];
    const float* Wk = (const float*)d_in[5];
    const float* bk = (const float*)d_in[6];
    const float* Wv = (const float*)d_in[7];
    const float* bv = (const float*)d_in[8];
    const float* Wo = (const float*)d_in[9];
    const float* bo = (const float*)d_in[10];
    float* out = (float*)d_out;

    float* gctx;
    __half *qh, *kh, *vh;
    __nv_bfloat16 *xhi, *xlo, *whi, *wlo;
    cudaGetSymbolAddress((void**)&gctx, g_ctx);
    cudaGetSymbolAddress((void**)&qh,   g_qh);
    cudaGetSymbolAddress((void**)&kh,   g_kh);
    cudaGetSymbolAddress((void**)&vh,   g_vh);
    cudaGetSymbolAddress((void**)&xhi,  g_xhi);
    cudaGetSymbolAddress((void**)&xlo,  g_xlo);
    cudaGetSymbolAddress((void**)&whi,  g_whi);
    cudaGetSymbolAddress((void**)&wlo,  g_wlo);

    cudaFuncSetAttribute(flash_attn_h,
                         cudaFuncAttributeMaxDynamicSharedMemorySize,
                         QS_B + 4 * KV_B);
    cudaFuncSetAttribute(gemm_tc<0>,
                         cudaFuncAttributeMaxDynamicSharedMemorySize, 2 * STAGE_B);
    cudaFuncSetAttribute(gemm_tc<1>,
                         cudaFuncAttributeMaxDynamicSharedMemorySize, 2 * STAGE_B);

    const int M = Bz * Sz;
    const int NX = M * Ez;
    const int NW = Ez * Ez;
    dim3 ggrid(Ez / 128, M / 128);

    conv_split<<<NX / 1024, 256>>>(Q, xhi, xlo, NX);
    conv_split<<<NW / 1024, 256>>>(Wq, whi, wlo, NW);
    gemm_tc<1><<<ggrid, 256, 2 * STAGE_B>>>(xhi, xlo, whi, wlo, bq, qh, M, Ez, Ez);

    conv_split<<<NX / 1024, 256>>>(K, xhi, xlo, NX);
    conv_split<<<NW / 1024, 256>>>(Wk, whi, wlo, NW);
    gemm_tc<1><<<ggrid, 256, 2 * STAGE_B>>>(xhi, xlo, whi, wlo, bk, kh, M, Ez, Ez);

    conv_split<<<NX / 1024, 256>>>(V, xhi, xlo, NX);
    conv_split<<<NW / 1024, 256>>>(Wv, whi, wlo, NW);
    gemm_tc<1><<<ggrid, 256, 2 * STAGE_B>>>(xhi, xlo, whi, wlo, bv, vh, M, Ez, Ez);

    flash_attn_h<<<dim3(Sz / 128, Hz, Bz), 256, QS_B + 4 * KV_B>>>(
        qh, kh, vh, gctx);

    conv_split<<<NX / 1024, 256>>>(gctx, xhi, xlo, NX);
    conv_split<<<NW / 1024, 256>>>(Wo, whi, wlo, NW);
    gemm_tc<0><<<ggrid, 256, 2 * STAGE_B>>>(xhi, xlo, whi, wlo, bo, out, M, Ez, Ez);
}

// round 5
// speedup vs baseline: 5.9908x; 1.7093x over previous
#include <cuda_runtime.h>
#include <cuda_fp16.h>
#include <math.h>
#include <stdint.h>

#define Bz 4
#define Sz 2048
#define Ez 1024
#define Hz 16
#define DKz 64

// ---------------------------------------------------------------------------
// Scratch (no allocs allowed)
// ---------------------------------------------------------------------------
__device__ __half g_qh[Bz * Sz * Ez];
__device__ __half g_kh[Bz * Sz * Ez];
__device__ __half g_vh[Bz * Sz * Ez];
__device__ __half g_ctxh[Bz * Sz * Ez];
__device__ __half g_xh[Bz * Sz * Ez];   // input conv buffer (reused Q,K,V)
__device__ __half g_wh[Ez * Ez];        // weight conv buffer (reused)

// ---------------------------------------------------------------------------
// Base-target PTX helpers (NO tcgen05 — harness compiles for sm_103 base)
// ---------------------------------------------------------------------------
__device__ __forceinline__ uint32_t smem_u32(const void* p) {
    uint32_t a;
    asm("{ .reg .u64 t; cvta.to.shared.u64 t, %1; cvt.u32.u64 %0, t; }"
        : "=r"(a) : "l"(p));
    return a;
}
__device__ __forceinline__ void cp16(uint32_t dst, const void* src) {
    asm volatile("cp.async.cg.shared.global [%0], [%1], 16;" :: "r"(dst), "l"(src));
}
__device__ __forceinline__ void cp_commit() {
    asm volatile("cp.async.commit_group;" ::: "memory");
}
template <int N>
__device__ __forceinline__ void cp_wait() {
    asm volatile("cp.async.wait_group %0;" :: "n"(N) : "memory");
}
__device__ __forceinline__ void ldsm4(uint32_t& r0, uint32_t& r1, uint32_t& r2,
                                      uint32_t& r3, uint32_t addr) {
    asm volatile("ldmatrix.sync.aligned.m8n8.x4.shared.b16 {%0,%1,%2,%3}, [%4];"
                 : "=r"(r0), "=r"(r1), "=r"(r2), "=r"(r3) : "r"(addr));
}
__device__ __forceinline__ void ldsm2(uint32_t& r0, uint32_t& r1, uint32_t addr) {
    asm volatile("ldmatrix.sync.aligned.m8n8.x2.shared.b16 {%0,%1}, [%2];"
                 : "=r"(r0), "=r"(r1) : "r"(addr));
}
__device__ __forceinline__ void ldsm2t(uint32_t& r0, uint32_t& r1, uint32_t addr) {
    asm volatile("ldmatrix.sync.aligned.m8n8.x2.trans.shared.b16 {%0,%1}, [%2];"
                 : "=r"(r0), "=r"(r1) : "r"(addr));
}
__device__ __forceinline__ void mma_fp(float* d, const uint32_t* a,
                                       const uint32_t* b) {
    asm volatile(
        "mma.sync.aligned.m16n8k16.row.col.f32.f16.f16.f32 "
        "{%0,%1,%2,%3}, {%4,%5,%6,%7}, {%8,%9}, {%0,%1,%2,%3};"
        : "+f"(d[0]), "+f"(d[1]), "+f"(d[2]), "+f"(d[3])
        : "r"(a[0]), "r"(a[1]), "r"(a[2]), "r"(a[3]), "r"(b[0]), "r"(b[1]));
}

// ---------------------------------------------------------------------------
// fp32 -> fp16 cast, 8 elems/thread
// ---------------------------------------------------------------------------
__global__ __launch_bounds__(256) void conv_h(
    const float* __restrict__ x, __half* __restrict__ y, int n)
{
    int i = (blockIdx.x * 256 + threadIdx.x) * 8;
    if (i >= n) return;
    float4 a = *(const float4*)&x[i];
    float4 b = *(const float4*)&x[i + 4];
    __half2 h[4];
    h[0] = __floats2half2_rn(a.x, a.y);
    h[1] = __floats2half2_rn(a.z, a.w);
    h[2] = __floats2half2_rn(b.x, b.y);
    h[3] = __floats2half2_rn(b.z, b.w);
    *(uint4*)&y[i] = *(uint4*)h;
}

// ---------------------------------------------------------------------------
// fp16 HMMA GEMM: O[M,N] = A[M,K] * B[N,K]^T + bias, fp32 accum.
// Tile 128x128x32, 8 warps (4M x 2N), 3-stage cp.async pipeline.
// Rows padded to 80B -> conflict-free ldmatrix. Stage = A|B = 20480B.
// HOUT=1 -> __half output; HOUT=0 -> fp32 output.
// ---------------------------------------------------------------------------
#define GBK 32
#define LDT 80
#define TILE_B 10240
#define STG_B 20480
#define NSTG 3

template <int HOUT>
__global__ __launch_bounds__(256) void gemm_h(
    const __half* __restrict__ A, const __half* __restrict__ Bm,
    const float* __restrict__ bias, void* __restrict__ Ov,
    int M, int N, int K)
{
    extern __shared__ __align__(128) char smem[];
    const int tid = threadIdx.x;
    const int wid = tid >> 5;
    const int lane = tid & 31;
    const int wm = (wid >> 1) * 32;
    const int wn = (wid & 1) * 64;
    const int m0 = blockIdx.y * 128;
    const int n0 = blockIdx.x * 128;

    const uint32_t sb = smem_u32(smem);
    const uint32_t arow = (uint32_t)(wm + (lane & 15)) * LDT + (lane >> 4) * 16;
    const uint32_t brow = (uint32_t)(wn + (lane & 7)) * LDT + ((lane >> 3) & 1) * 16;

    float acc[2][8][4];
#pragma unroll
    for (int mt = 0; mt < 2; mt++)
#pragma unroll
        for (int nt = 0; nt < 8; nt++)
#pragma unroll
            for (int i = 0; i < 4; i++) acc[mt][nt][i] = 0.0f;

    const int NIT = K / GBK;

    auto load_stage = [&](int it, int slot) {
        const uint32_t stb = sb + slot * STG_B;
        const int k0 = it * GBK;
#pragma unroll
        for (int half = 0; half < 2; half++) {
            int c = tid + half * 256;
            int row = c >> 2, ch = c & 3;
            uint32_t so = (uint32_t)row * LDT + ch * 16;
            cp16(stb + so,          A  + (size_t)(m0 + row) * K + k0 + ch * 8);
            cp16(stb + TILE_B + so, Bm + (size_t)(n0 + row) * K + k0 + ch * 8);
        }
        cp_commit();
    };

    load_stage(0, 0);
    load_stage(1, 1);

#pragma unroll 1
    for (int it = 0; it < NIT; it++) {
        const int slot = it % NSTG;
        if (it < NIT - 1) cp_wait<1>(); else cp_wait<0>();
        __syncthreads();
        if (it + 2 < NIT) load_stage(it + 2, (it + 2) % NSTG);

        const uint32_t Ab = sb + slot * STG_B;
        const uint32_t Bb = Ab + TILE_B;
#pragma unroll
        for (int ks = 0; ks < 2; ks++) {
            uint32_t a[2][4];
#pragma unroll
            for (int mt = 0; mt < 2; mt++) {
                uint32_t ao = arow + (uint32_t)mt * (16 * LDT) + ks * 32;
                ldsm4(a[mt][0], a[mt][1], a[mt][2], a[mt][3], Ab + ao);
            }
#pragma unroll
            for (int nt = 0; nt < 8; nt++) {
                uint32_t b2[2];
                ldsm2(b2[0], b2[1], Bb + brow + nt * (8 * LDT) + ks * 32);
#pragma unroll
                for (int mt = 0; mt < 2; mt++)
                    mma_fp(acc[mt][nt], a[mt], b2);
            }
        }
        __syncthreads();
    }

    const int r0 = m0 + wm + (lane >> 2);
    const int c0 = n0 + wn + 2 * (lane & 3);
#pragma unroll
    for (int mt = 0; mt < 2; mt++) {
#pragma unroll
        for (int nt = 0; nt < 8; nt++) {
            int cc = c0 + nt * 8;
            float bx = __ldg(&bias[cc]);
            float by = __ldg(&bias[cc + 1]);
            int ra = r0 + mt * 16;
            if (HOUT) {
                __half2* O = (__half2*)Ov;
                O[((size_t)ra * N + cc) / 2] =
                    __floats2half2_rn(acc[mt][nt][0] + bx, acc[mt][nt][1] + by);
                O[((size_t)(ra + 8) * N + cc) / 2] =
                    __floats2half2_rn(acc[mt][nt][2] + bx, acc[mt][nt][3] + by);
            } else {
                float* O = (float*)Ov;
                *(float2*)&O[(size_t)ra * N + cc] =
                    make_float2(acc[mt][nt][0] + bx, acc[mt][nt][1] + by);
                *(float2*)&O[(size_t)(ra + 8) * N + cc] =
                    make_float2(acc[mt][nt][2] + bx, acc[mt][nt][3] + by);
            }
        }
    }
}

// ---------------------------------------------------------------------------
// Flash attention, fp16 HMMA, fp32 online softmax, fp16 ctx output.
// CTA: 128 Q rows x one (b,h); 8 warps x 16 rows. K/V tiles 64 keys,
// double-buffered cp.async. Rows padded to 144B (conflict-free ldsm).
// ---------------------------------------------------------------------------
#define LDH 144
#define QS_B (128 * LDH)
#define KV_B (64 * LDH)

__global__ __launch_bounds__(256) void flash_attn_h(
    const __half* __restrict__ Qg, const __half* __restrict__ Kg,
    const __half* __restrict__ Vg, __half* __restrict__ Og)
{
    extern __shared__ __align__(128) char smem[];
    const int tid = threadIdx.x;
    const int wid = tid >> 5;
    const int lane = tid & 31;
    const int qt = blockIdx.x;
    const int h  = blockIdx.y;
    const int b  = blockIdx.z;

    const uint32_t sb = smem_u32(smem);
    const size_t hb = (size_t)b * Sz * Ez + (size_t)h * DKz;
    const __half* qg = Qg + hb + (size_t)qt * 128 * Ez;
    const __half* kg = Kg + hb;
    const __half* vg = Vg + hb;

#pragma unroll
    for (int i = 0; i < 4; i++) {
        int c = tid + i * 256;
        int row = c >> 3, ch = c & 7;
        cp16(sb + row * LDH + ch * 16, qg + (size_t)row * Ez + ch * 8);
    }
    cp_commit();

    auto load_kv = [&](int kt, int s) {
        const uint32_t kb = sb + QS_B + s * 2 * KV_B;
        const __half* kp = kg + (size_t)(kt * 64) * Ez;
        const __half* vp = vg + (size_t)(kt * 64) * Ez;
#pragma unroll
        for (int i = 0; i < 4; i++) {
            int c = tid + i * 256;
            int row = c >> 3, ch = c & 7;
            if (row < 64)
                cp16(kb + row * LDH + ch * 16, kp + (size_t)row * Ez + ch * 8);
            else
                cp16(kb + KV_B + (row - 64) * LDH + ch * 16,
                     vp + (size_t)(row - 64) * Ez + ch * 8);
        }
        cp_commit();
    };

    load_kv(0, 0);

    const uint32_t arow = (uint32_t)(wid * 16 + (lane & 15)) * LDH +
                          (lane >> 4) * 16;
    const uint32_t brow = (uint32_t)(lane & 7) * LDH + ((lane >> 3) & 1) * 16;
    const uint32_t vrow = (uint32_t)(lane & 15) * LDH;

    float o[8][4];
#pragma unroll
    for (int nt = 0; nt < 8; nt++)
#pragma unroll
        for (int i = 0; i < 4; i++) o[nt][i] = 0.0f;
    float m0 = -INFINITY, m1 = -INFINITY, l0 = 0.0f, l1 = 0.0f;

    const int NT = Sz / 64;
#pragma unroll 1
    for (int it = 0; it < NT; it++) {
        const int s = it & 1;
        const bool pf = (it + 1 < NT);
        if (pf) load_kv(it + 1, s ^ 1);
        if (pf) cp_wait<1>(); else cp_wait<0>();
        __syncthreads();

        const uint32_t Kb = sb + QS_B + s * 2 * KV_B;
        const uint32_t Vb = Kb + KV_B;

        float sv[8][4];
#pragma unroll
        for (int nt = 0; nt < 8; nt++)
#pragma unroll
            for (int i = 0; i < 4; i++) sv[nt][i] = 0.0f;
#pragma unroll
        for (int ks = 0; ks < 4; ks++) {
            uint32_t qa[4];
            ldsm4(qa[0], qa[1], qa[2], qa[3], sb + arow + ks * 32);
#pragma unroll
            for (int nt = 0; nt < 8; nt++) {
                uint32_t kb2[2];
                ldsm2(kb2[0], kb2[1], Kb + brow + nt * (8 * LDH) + ks * 32);
                mma_fp(sv[nt], qa, kb2);
            }
        }

        float mx0 = -INFINITY, mx1 = -INFINITY;
#pragma unroll
        for (int nt = 0; nt < 8; nt++) {
            sv[nt][0] *= 0.125f; sv[nt][1] *= 0.125f;
            sv[nt][2] *= 0.125f; sv[nt][3] *= 0.125f;
            mx0 = fmaxf(mx0, fmaxf(sv[nt][0], sv[nt][1]));
            mx1 = fmaxf(mx1, fmaxf(sv[nt][2], sv[nt][3]));
        }
        mx0 = fmaxf(mx0, __shfl_xor_sync(0xffffffffu, mx0, 1));
        mx0 = fmaxf(mx0, __shfl_xor_sync(0xffffffffu, mx0, 2));
        mx1 = fmaxf(mx1, __shfl_xor_sync(0xffffffffu, mx1, 1));
        mx1 = fmaxf(mx1, __shfl_xor_sync(0xffffffffu, mx1, 2));
        float mn0 = fmaxf(m0, mx0), mn1 = fmaxf(m1, mx1);
        float cr0 = __expf(m0 - mn0), cr1 = __expf(m1 - mn1);
        float sum0 = 0.0f, sum1 = 0.0f;
#pragma unroll
        for (int nt = 0; nt < 8; nt++) {
            sv[nt][0] = __expf(sv[nt][0] - mn0);
            sv[nt][1] = __expf(sv[nt][1] - mn0);
            sv[nt][2] = __expf(sv[nt][2] - mn1);
            sv[nt][3] = __expf(sv[nt][3] - mn1);
            sum0 += sv[nt][0] + sv[nt][1];
            sum1 += sv[nt][2] + sv[nt][3];
        }
        sum0 += __shfl_xor_sync(0xffffffffu, sum0, 1);
        sum0 += __shfl_xor_sync(0xffffffffu, sum0, 2);
        sum1 += __shfl_xor_sync(0xffffffffu, sum1, 1);
        sum1 += __shfl_xor_sync(0xffffffffu, sum1, 2);
        l0 = l0 * cr0 + sum0;
        l1 = l1 * cr1 + sum1;
        m0 = mn0; m1 = mn1;
#pragma unroll
        for (int nt = 0; nt < 8; nt++) {
            o[nt][0] *= cr0; o[nt][1] *= cr0;
            o[nt][2] *= cr1; o[nt][3] *= cr1;
        }

#pragma unroll
        for (int ks = 0; ks < 4; ks++) {
            uint32_t pa[4];
            __half2 h0h = __floats2half2_rn(sv[2 * ks][0], sv[2 * ks][1]);
            __half2 h1h = __floats2half2_rn(sv[2 * ks][2], sv[2 * ks][3]);
            __half2 h2h = __floats2half2_rn(sv[2 * ks + 1][0], sv[2 * ks + 1][1]);
            __half2 h3h = __floats2half2_rn(sv[2 * ks + 1][2], sv[2 * ks + 1][3]);
            pa[0] = *(uint32_t*)&h0h; pa[1] = *(uint32_t*)&h1h;
            pa[2] = *(uint32_t*)&h2h; pa[3] = *(uint32_t*)&h3h;
#pragma unroll
            for (int nt = 0; nt < 8; nt++) {
                uint32_t vb2[2];
                ldsm2t(vb2[0], vb2[1], Vb + vrow + ks * (16 * LDH) + nt * 16);
                mma_fp(o[nt], pa, vb2);
            }
        }
        __syncthreads();
    }

    // write ctx[b, s, h*64+dk] as fp16
    const float i0 = 1.0f / l0, i1 = 1.0f / l1;
    const int gr0 = qt * 128 + wid * 16 + (lane >> 2);
    const int cbase = h * 64 + 2 * (lane & 3);
#pragma unroll
    for (int nt = 0; nt < 8; nt++) {
        int cc = cbase + nt * 8;
        *(__half2*)&Og[((size_t)(b * Sz + gr0)) * Ez + cc] =
            __floats2half2_rn(o[nt][0] * i0, o[nt][1] * i0);
        *(__half2*)&Og[((size_t)(b * Sz + gr0 + 8)) * Ez + cc] =
            __floats2half2_rn(o[nt][2] * i1, o[nt][3] * i1);
    }
}

// ---------------------------------------------------------------------------
extern "C" void kernel_launch(void* const* d_in, const int* in_sizes, int n_in,
                              void* d_out, int out_size)
{
    const float* Q  = (const float*)d_in[0];
    const float* K  = (const float*)d_in[1];
    const float* V  = (const float*)d_in[2];
    const float* Wq = (const float*)d_in[3];
    const float* bq = (const float*)d_in[4];
    const float* Wk = (const float*)d_in[5];
    const float* bk = (const float*)d_in[6];
    const float* Wv = (const float*)d_in[7];
    const float* bv = (const float*)d_in[8];
    const float* Wo = (const float*)d_in[9];
    const float* bo = (const float*)d_in[10];
    float* out = (float*)d_out;

    __half *qh, *kh, *vh, *ctxh, *xh, *wh;
    cudaGetSymbolAddress((void**)&qh,   g_qh);
    cudaGetSymbolAddress((void**)&kh,   g_kh);
    cudaGetSymbolAddress((void**)&vh,   g_vh);
    cudaGetSymbolAddress((void**)&ctxh, g_ctxh);
    cudaGetSymbolAddress((void**)&xh,   g_xh);
    cudaGetSymbolAddress((void**)&wh,   g_wh);

    cudaFuncSetAttribute(flash_attn_h,
                         cudaFuncAttributeMaxDynamicSharedMemorySize,
                         QS_B + 4 * KV_B);
    cudaFuncSetAttribute(gemm_h<0>,
                         cudaFuncAttributeMaxDynamicSharedMemorySize, NSTG * STG_B);
    cudaFuncSetAttribute(gemm_h<1>,
                         cudaFuncAttributeMaxDynamicSharedMemorySize, NSTG * STG_B);

    const int M = Bz * Sz;
    const int NX = M * Ez;
    const int NW = Ez * Ez;
    dim3 ggrid(Ez / 128, M / 128);

    conv_h<<<NX / 2048, 256>>>(Q, xh, NX);
    conv_h<<<NW / 2048, 256>>>(Wq, wh, NW);
    gemm_h<1><<<ggrid, 256, NSTG * STG_B>>>(xh, wh, bq, qh, M, Ez, Ez);

    conv_h<<<NX / 2048, 256>>>(K, xh, NX);
    conv_h<<<NW / 2048, 256>>>(Wk, wh, NW);
    gemm_h<1><<<ggrid, 256, NSTG * STG_B>>>(xh, wh, bk, kh, M, Ez, Ez);

    conv_h<<<NX / 2048, 256>>>(V, xh, NX);
    conv_h<<<NW / 2048, 256>>>(Wv, wh, NW);
    gemm_h<1><<<ggrid, 256, NSTG * STG_B>>>(xh, wh, bv, vh, M, Ez, Ez);

    flash_attn_h<<<dim3(Sz / 128, Hz, Bz), 256, QS_B + 4 * KV_B>>>(
        qh, kh, vh, ctxh);

    conv_h<<<NW / 2048, 256>>>(Wo, wh, NW);
    gemm_h<0><<<ggrid, 256, NSTG * STG_B>>>(ctxh, wh, bo, out, M, Ez, Ez);
}

// round 6
// speedup vs baseline: 6.6834x; 1.1156x over previous
#include <cuda_runtime.h>
#include <cuda_fp16.h>
#include <math.h>
#include <stdint.h>

#define Bz 4
#define Sz 2048
#define Ez 1024
#define Hz 16
#define DKz 64

#define CNX (Bz * Sz * Ez)   // 8388608
#define CNW (Ez * Ez)        // 1048576
#define BLKX (CNX / 2048)    // 4096
#define BLKW (CNW / 2048)    // 512

// ---------------------------------------------------------------------------
// Scratch (no allocs allowed)
// ---------------------------------------------------------------------------
__device__ __half g_x3[3 * CNX];    // converted Q,K,V inputs (contiguous)
__device__ __half g_w3[3 * CNW];    // converted Wq,Wk,Wv (contiguous)
__device__ __half g_wo[CNW];        // converted Wo
__device__ __half g_qkv[3 * CNX];   // projected q,k,v (contiguous)
__device__ __half g_ctxh[CNX];      // attention context

// ---------------------------------------------------------------------------
// Base-target PTX helpers (NO tcgen05 — harness compiles for sm_103 base)
// ---------------------------------------------------------------------------
__device__ __forceinline__ uint32_t smem_u32(const void* p) {
    uint32_t a;
    asm("{ .reg .u64 t; cvta.to.shared.u64 t, %1; cvt.u32.u64 %0, t; }"
        : "=r"(a) : "l"(p));
    return a;
}
__device__ __forceinline__ void cp16(uint32_t dst, const void* src) {
    asm volatile("cp.async.cg.shared.global [%0], [%1], 16;" :: "r"(dst), "l"(src));
}
__device__ __forceinline__ void cp_commit() {
    asm volatile("cp.async.commit_group;" ::: "memory");
}
template <int N>
__device__ __forceinline__ void cp_wait() {
    asm volatile("cp.async.wait_group %0;" :: "n"(N) : "memory");
}
__device__ __forceinline__ void ldsm4(uint32_t& r0, uint32_t& r1, uint32_t& r2,
                                      uint32_t& r3, uint32_t addr) {
    asm volatile("ldmatrix.sync.aligned.m8n8.x4.shared.b16 {%0,%1,%2,%3}, [%4];"
                 : "=r"(r0), "=r"(r1), "=r"(r2), "=r"(r3) : "r"(addr));
}
__device__ __forceinline__ void ldsm4t(uint32_t& r0, uint32_t& r1, uint32_t& r2,
                                       uint32_t& r3, uint32_t addr) {
    asm volatile("ldmatrix.sync.aligned.m8n8.x4.trans.shared.b16 {%0,%1,%2,%3}, [%4];"
                 : "=r"(r0), "=r"(r1), "=r"(r2), "=r"(r3) : "r"(addr));
}
__device__ __forceinline__ void mma_fp(float* d, const uint32_t* a,
                                       const uint32_t* b) {
    asm volatile(
        "mma.sync.aligned.m16n8k16.row.col.f32.f16.f16.f32 "
        "{%0,%1,%2,%3}, {%4,%5,%6,%7}, {%8,%9}, {%0,%1,%2,%3};"
        : "+f"(d[0]), "+f"(d[1]), "+f"(d[2]), "+f"(d[3])
        : "r"(a[0]), "r"(a[1]), "r"(a[2]), "r"(a[3]), "r"(b[0]), "r"(b[1]));
}

// ---------------------------------------------------------------------------
// One fused fp32 -> fp16 conversion for all 7 tensors.
// Segments: [3 x BLKX] for Q,K,V -> x3; [4 x BLKW] for Wq,Wk,Wv -> w3, Wo -> wo.
// ---------------------------------------------------------------------------
__device__ __forceinline__ void conv8(const float* __restrict__ s,
                                      __half* __restrict__ d, int i) {
    float4 a = *(const float4*)&s[i];
    float4 b = *(const float4*)&s[i + 4];
    __half2 h[4];
    h[0] = __floats2half2_rn(a.x, a.y);
    h[1] = __floats2half2_rn(a.z, a.w);
    h[2] = __floats2half2_rn(b.x, b.y);
    h[3] = __floats2half2_rn(b.z, b.w);
    *(uint4*)&d[i] = *(uint4*)h;
}

__global__ __launch_bounds__(256) void conv_all(
    const float* __restrict__ Q, const float* __restrict__ K,
    const float* __restrict__ V, const float* __restrict__ Wq,
    const float* __restrict__ Wk, const float* __restrict__ Wv,
    const float* __restrict__ Wo, __half* __restrict__ x3,
    __half* __restrict__ w3, __half* __restrict__ wo)
{
    const int bid = blockIdx.x;
    if (bid < 3 * BLKX) {
        const int seg = bid / BLKX;
        const int lb = bid - seg * BLKX;
        const float* src = (seg == 0) ? Q : (seg == 1) ? K : V;
        __half* dst = x3 + (size_t)seg * CNX;
        conv8(src, dst, lb * 2048 + threadIdx.x * 8);
    } else {
        const int r = bid - 3 * BLKX;
        const int seg = r / BLKW;
        const int lb = r - seg * BLKW;
        const float* src = (seg == 0) ? Wq : (seg == 1) ? Wk
                          : (seg == 2) ? Wv : Wo;
        __half* dst = (seg < 3) ? (w3 + (size_t)seg * CNW) : wo;
        conv8(src, dst, lb * 2048 + threadIdx.x * 8);
    }
}

// ---------------------------------------------------------------------------
// fp16 HMMA GEMM: O[z][M,N] = A[z][M,K] * W[z][N,K]^T + bias[z], fp32 accum.
// Tile 128x128x32, 8 warps (4M x 2N), 3-stage cp.async, ONE sync per iter.
// NZ=3 -> fused QKV (blockIdx.z selects slice); NZ=1 -> single GEMM.
// HOUT=1 -> __half out; HOUT=0 -> fp32 out.
// ---------------------------------------------------------------------------
#define GBK 32
#define LDT 80
#define TILE_B 10240
#define STG_B 20480
#define NSTG 3

template <int NZ, int HOUT>
__global__ __launch_bounds__(256) void gemm_h(
    const __half* __restrict__ A0, const __half* __restrict__ W0,
    const float* __restrict__ bz0, const float* __restrict__ bz1,
    const float* __restrict__ bz2, void* __restrict__ Ov,
    int M, int N, int K)
{
    extern __shared__ __align__(128) char smem[];
    const int z = (NZ > 1) ? blockIdx.z : 0;
    const __half* A  = A0 + (size_t)z * M * K;
    const __half* Bm = W0 + (size_t)z * N * K;
    const float* bias = (z == 0) ? bz0 : (z == 1) ? bz1 : bz2;

    const int tid = threadIdx.x;
    const int wid = tid >> 5;
    const int lane = tid & 31;
    const int wm = (wid >> 1) * 32;
    const int wn = (wid & 1) * 64;
    const int m0 = blockIdx.y * 128;
    const int n0 = blockIdx.x * 128;

    const uint32_t sb = smem_u32(smem);
    const uint32_t arow = (uint32_t)(wm + (lane & 15)) * LDT + (lane >> 4) * 16;
    // ldsm4 B: lanes 0-7 -> (nt even, k0-7), 8-15 -> (nt even, k8-15),
    //          16-23 -> (nt odd, k0-7), 24-31 -> (nt odd, k8-15)
    const uint32_t bbase = (uint32_t)(wn + (lane >> 4) * 8 + (lane & 7)) * LDT +
                           ((lane >> 3) & 1) * 16;

    float acc[2][8][4];
#pragma unroll
    for (int mt = 0; mt < 2; mt++)
#pragma unroll
        for (int nt = 0; nt < 8; nt++)
#pragma unroll
            for (int i = 0; i < 4; i++) acc[mt][nt][i] = 0.0f;

    const int NIT = K / GBK;

    auto load_stage = [&](int it, int slot) {
        const uint32_t stb = sb + slot * STG_B;
        const int k0 = it * GBK;
#pragma unroll
        for (int half = 0; half < 2; half++) {
            int c = tid + half * 256;
            int row = c >> 2, ch = c & 3;
            uint32_t so = (uint32_t)row * LDT + ch * 16;
            cp16(stb + so,          A  + (size_t)(m0 + row) * K + k0 + ch * 8);
            cp16(stb + TILE_B + so, Bm + (size_t)(n0 + row) * K + k0 + ch * 8);
        }
        cp_commit();
    };

    load_stage(0, 0);
    load_stage(1, 1);

#pragma unroll 1
    for (int it = 0; it < NIT; it++) {
        const int slot = it % NSTG;
        if (it < NIT - 1) cp_wait<1>(); else cp_wait<0>();
        __syncthreads();   // single barrier: orders consume(it-1) < load(it+2)
        if (it + 2 < NIT) load_stage(it + 2, (it + 2) % NSTG);

        const uint32_t Ab = sb + slot * STG_B;
        const uint32_t Bb = Ab + TILE_B;
#pragma unroll
        for (int ks = 0; ks < 2; ks++) {
            uint32_t a[2][4];
#pragma unroll
            for (int mt = 0; mt < 2; mt++) {
                uint32_t ao = arow + (uint32_t)mt * (16 * LDT) + ks * 32;
                ldsm4(a[mt][0], a[mt][1], a[mt][2], a[mt][3], Ab + ao);
            }
#pragma unroll
            for (int np = 0; np < 4; np++) {
                uint32_t b4[4];
                ldsm4(b4[0], b4[1], b4[2], b4[3],
                      Bb + bbase + np * (16 * LDT) + ks * 32);
#pragma unroll
                for (int mt = 0; mt < 2; mt++) {
                    mma_fp(acc[mt][2 * np],     a[mt], b4);
                    mma_fp(acc[mt][2 * np + 1], a[mt], b4 + 2);
                }
            }
        }
    }

    __syncthreads();
    const int r0 = m0 + wm + (lane >> 2);
    const int c0 = n0 + wn + 2 * (lane & 3);
#pragma unroll
    for (int mt = 0; mt < 2; mt++) {
#pragma unroll
        for (int nt = 0; nt < 8; nt++) {
            int cc = c0 + nt * 8;
            float bx = __ldg(&bias[cc]);
            float by = __ldg(&bias[cc + 1]);
            int ra = r0 + mt * 16;
            if (HOUT) {
                __half2* O = (__half2*)Ov + (size_t)z * M * N / 2;
                O[((size_t)ra * N + cc) / 2] =
                    __floats2half2_rn(acc[mt][nt][0] + bx, acc[mt][nt][1] + by);
                O[((size_t)(ra + 8) * N + cc) / 2] =
                    __floats2half2_rn(acc[mt][nt][2] + bx, acc[mt][nt][3] + by);
            } else {
                float* O = (float*)Ov + (size_t)z * M * N;
                *(float2*)&O[(size_t)ra * N + cc] =
                    make_float2(acc[mt][nt][0] + bx, acc[mt][nt][1] + by);
                *(float2*)&O[(size_t)(ra + 8) * N + cc] =
                    make_float2(acc[mt][nt][2] + bx, acc[mt][nt][3] + by);
            }
        }
    }
}

// ---------------------------------------------------------------------------
// Flash attention, fp16 HMMA, fp32 online softmax, fp16 ctx output.
// CTA: 128 Q rows x one (b,h); 8 warps x 16 rows. K/V tiles 64 keys,
// double-buffered cp.async (2 syncs/iter required at 2 stages).
// Rows padded to 144B -> conflict-free ldsm.
// ---------------------------------------------------------------------------
#define LDH 144
#define QS_B (128 * LDH)
#define KV_B (64 * LDH)

__global__ __launch_bounds__(256) void flash_attn_h(
    const __half* __restrict__ Qg, const __half* __restrict__ Kg,
    const __half* __restrict__ Vg, __half* __restrict__ Og)
{
    extern __shared__ __align__(128) char smem[];
    const int tid = threadIdx.x;
    const int wid = tid >> 5;
    const int lane = tid & 31;
    const int qt = blockIdx.x;
    const int h  = blockIdx.y;
    const int b  = blockIdx.z;

    const uint32_t sb = smem_u32(smem);
    const size_t hb = (size_t)b * Sz * Ez + (size_t)h * DKz;
    const __half* qg = Qg + hb + (size_t)qt * 128 * Ez;
    const __half* kg = Kg + hb;
    const __half* vg = Vg + hb;

#pragma unroll
    for (int i = 0; i < 4; i++) {
        int c = tid + i * 256;
        int row = c >> 3, ch = c & 7;
        cp16(sb + row * LDH + ch * 16, qg + (size_t)row * Ez + ch * 8);
    }
    cp_commit();

    auto load_kv = [&](int kt, int s) {
        const uint32_t kb = sb + QS_B + s * 2 * KV_B;
        const __half* kp = kg + (size_t)(kt * 64) * Ez;
        const __half* vp = vg + (size_t)(kt * 64) * Ez;
#pragma unroll
        for (int i = 0; i < 4; i++) {
            int c = tid + i * 256;
            int row = c >> 3, ch = c & 7;
            if (row < 64)
                cp16(kb + row * LDH + ch * 16, kp + (size_t)row * Ez + ch * 8);
            else
                cp16(kb + KV_B + (row - 64) * LDH + ch * 16,
                     vp + (size_t)(row - 64) * Ez + ch * 8);
        }
        cp_commit();
    };

    load_kv(0, 0);

    const uint32_t arow = (uint32_t)(wid * 16 + (lane & 15)) * LDH +
                          (lane >> 4) * 16;
    const uint32_t bbase = (uint32_t)((lane >> 4) * 8 + (lane & 7)) * LDH +
                           ((lane >> 3) & 1) * 16;
    const uint32_t vbase = (uint32_t)(lane & 15) * LDH + (lane >> 4) * 16;

    float o[8][4];
#pragma unroll
    for (int nt = 0; nt < 8; nt++)
#pragma unroll
        for (int i = 0; i < 4; i++) o[nt][i] = 0.0f;
    float m0 = -INFINITY, m1 = -INFINITY, l0 = 0.0f, l1 = 0.0f;

    const int NT = Sz / 64;
#pragma unroll 1
    for (int it = 0; it < NT; it++) {
        const int s = it & 1;
        const bool pf = (it + 1 < NT);
        if (pf) load_kv(it + 1, s ^ 1);
        if (pf) cp_wait<1>(); else cp_wait<0>();
        __syncthreads();

        const uint32_t Kb = sb + QS_B + s * 2 * KV_B;
        const uint32_t Vb = Kb + KV_B;

        float sv[8][4];
#pragma unroll
        for (int nt = 0; nt < 8; nt++)
#pragma unroll
            for (int i = 0; i < 4; i++) sv[nt][i] = 0.0f;
#pragma unroll
        for (int ks = 0; ks < 4; ks++) {
            uint32_t qa[4];
            ldsm4(qa[0], qa[1], qa[2], qa[3], sb + arow + ks * 32);
#pragma unroll
            for (int np = 0; np < 4; np++) {
                uint32_t b4[4];
                ldsm4(b4[0], b4[1], b4[2], b4[3],
                      Kb + bbase + np * (16 * LDH) + ks * 32);
                mma_fp(sv[2 * np],     qa, b4);
                mma_fp(sv[2 * np + 1], qa, b4 + 2);
            }
        }

        float mx0 = -INFINITY, mx1 = -INFINITY;
#pragma unroll
        for (int nt = 0; nt < 8; nt++) {
            sv[nt][0] *= 0.125f; sv[nt][1] *= 0.125f;
            sv[nt][2] *= 0.125f; sv[nt][3] *= 0.125f;
            mx0 = fmaxf(mx0, fmaxf(sv[nt][0], sv[nt][1]));
            mx1 = fmaxf(mx1, fmaxf(sv[nt][2], sv[nt][3]));
        }
        mx0 = fmaxf(mx0, __shfl_xor_sync(0xffffffffu, mx0, 1));
        mx0 = fmaxf(mx0, __shfl_xor_sync(0xffffffffu, mx0, 2));
        mx1 = fmaxf(mx1, __shfl_xor_sync(0xffffffffu, mx1, 1));
        mx1 = fmaxf(mx1, __shfl_xor_sync(0xffffffffu, mx1, 2));
        float mn0 = fmaxf(m0, mx0), mn1 = fmaxf(m1, mx1);
        float cr0 = __expf(m0 - mn0), cr1 = __expf(m1 - mn1);
        float sum0 = 0.0f, sum1 = 0.0f;
#pragma unroll
        for (int nt = 0; nt < 8; nt++) {
            sv[nt][0] = __expf(sv[nt][0] - mn0);
            sv[nt][1] = __expf(sv[nt][1] - mn0);
            sv[nt][2] = __expf(sv[nt][2] - mn1);
            sv[nt][3] = __expf(sv[nt][3] - mn1);
            sum0 += sv[nt][0] + sv[nt][1];
            sum1 += sv[nt][2] + sv[nt][3];
        }
        sum0 += __shfl_xor_sync(0xffffffffu, sum0, 1);
        sum0 += __shfl_xor_sync(0xffffffffu, sum0, 2);
        sum1 += __shfl_xor_sync(0xffffffffu, sum1, 1);
        sum1 += __shfl_xor_sync(0xffffffffu, sum1, 2);
        l0 = l0 * cr0 + sum0;
        l1 = l1 * cr1 + sum1;
        m0 = mn0; m1 = mn1;
#pragma unroll
        for (int nt = 0; nt < 8; nt++) {
            o[nt][0] *= cr0; o[nt][1] *= cr0;
            o[nt][2] *= cr1; o[nt][3] *= cr1;
        }

#pragma unroll
        for (int ks = 0; ks < 4; ks++) {
            uint32_t pa[4];
            __half2 h0h = __floats2half2_rn(sv[2 * ks][0], sv[2 * ks][1]);
            __half2 h1h = __floats2half2_rn(sv[2 * ks][2], sv[2 * ks][3]);
            __half2 h2h = __floats2half2_rn(sv[2 * ks + 1][0], sv[2 * ks + 1][1]);
            __half2 h3h = __floats2half2_rn(sv[2 * ks + 1][2], sv[2 * ks + 1][3]);
            pa[0] = *(uint32_t*)&h0h; pa[1] = *(uint32_t*)&h1h;
            pa[2] = *(uint32_t*)&h2h; pa[3] = *(uint32_t*)&h3h;
#pragma unroll
            for (int np = 0; np < 4; np++) {
                uint32_t v4[4];
                ldsm4t(v4[0], v4[1], v4[2], v4[3],
                       Vb + vbase + ks * (16 * LDH) + np * 32);
                mma_fp(o[2 * np],     pa, v4);
                mma_fp(o[2 * np + 1], pa, v4 + 2);
            }
        }
        __syncthreads();
    }

    const float i0 = 1.0f / l0, i1 = 1.0f / l1;
    const int gr0 = qt * 128 + wid * 16 + (lane >> 2);
    const int cbase = h * 64 + 2 * (lane & 3);
#pragma unroll
    for (int nt = 0; nt < 8; nt++) {
        int cc = cbase + nt * 8;
        *(__half2*)&Og[((size_t)(b * Sz + gr0)) * Ez + cc] =
            __floats2half2_rn(o[nt][0] * i0, o[nt][1] * i0);
        *(__half2*)&Og[((size_t)(b * Sz + gr0 + 8)) * Ez + cc] =
            __floats2half2_rn(o[nt][2] * i1, o[nt][3] * i1);
    }
}

// ---------------------------------------------------------------------------
extern "C" void kernel_launch(void* const* d_in, const int* in_sizes, int n_in,
                              void* d_out, int out_size)
{
    const float* Q  = (const float*)d_in[0];
    const float* K  = (const float*)d_in[1];
    const float* V  = (const float*)d_in[2];
    const float* Wq = (const float*)d_in[3];
    const float* bq = (const float*)d_in[4];
    const float* Wk = (const float*)d_in[5];
    const float* bk = (const float*)d_in[6];
    const float* Wv = (const float*)d_in[7];
    const float* bv = (const float*)d_in[8];
    const float* Wo = (const float*)d_in[9];
    const float* bo = (const float*)d_in[10];
    float* out = (float*)d_out;

    __half *x3, *w3, *wo, *qkv, *ctxh;
    cudaGetSymbolAddress((void**)&x3,   g_x3);
    cudaGetSymbolAddress((void**)&w3,   g_w3);
    cudaGetSymbolAddress((void**)&wo,   g_wo);
    cudaGetSymbolAddress((void**)&qkv,  g_qkv);
    cudaGetSymbolAddress((void**)&ctxh, g_ctxh);

    cudaFuncSetAttribute(flash_attn_h,
                         cudaFuncAttributeMaxDynamicSharedMemorySize,
                         QS_B + 4 * KV_B);
    cudaFuncSetAttribute(gemm_h<3, 1>,
                         cudaFuncAttributeMaxDynamicSharedMemorySize, NSTG * STG_B);
    cudaFuncSetAttribute(gemm_h<1, 0>,
                         cudaFuncAttributeMaxDynamicSharedMemorySize, NSTG * STG_B);

    const int M = Bz * Sz;

    // one conversion kernel for everything
    conv_all<<<3 * BLKX + 4 * BLKW, 256>>>(Q, K, V, Wq, Wk, Wv, Wo, x3, w3, wo);

    // fused QKV projection
    gemm_h<3, 1><<<dim3(Ez / 128, M / 128, 3), 256, NSTG * STG_B>>>(
        x3, w3, bq, bk, bv, qkv, M, Ez, Ez);

    // attention
    flash_attn_h<<<dim3(Sz / 128, Hz, Bz), 256, QS_B + 4 * KV_B>>>(
        qkv, qkv + (size_t)CNX, qkv + 2 * (size_t)CNX, ctxh);

    // output projection
    gemm_h<1, 0><<<dim3(Ez / 128, M / 128, 1), 256, NSTG * STG_B>>>(
        ctxh, wo, bo, bo, bo, out, M, Ez, Ez);
}

// round 7
// speedup vs baseline: 7.0850x; 1.0601x over previous
#include <cuda_runtime.h>
#include <cuda_fp16.h>
#include <math.h>
#include <stdint.h>

#define Bz 4
#define Sz 2048
#define Ez 1024
#define Hz 16
#define DKz 64

#define CNX (Bz * Sz * Ez)   // 8388608
#define CNW (Ez * Ez)        // 1048576
#define BLKX (CNX / 2048)    // 4096
#define BLKW (CNW / 2048)    // 512

// ---------------------------------------------------------------------------
// Scratch (no allocs allowed)
// ---------------------------------------------------------------------------
__device__ __half g_x3[3 * CNX];    // converted Q,K,V inputs (contiguous)
__device__ __half g_w3[3 * CNW];    // converted Wq,Wk,Wv (contiguous)
__device__ __half g_wo[CNW];        // converted Wo
__device__ __half g_qkv[3 * CNX];   // projected q,k,v (contiguous)
__device__ __half g_ctxh[CNX];      // attention context

// ---------------------------------------------------------------------------
// Base-target PTX helpers (NO tcgen05 — harness compiles for sm_103 base)
// ---------------------------------------------------------------------------
__device__ __forceinline__ uint32_t smem_u32(const void* p) {
    uint32_t a;
    asm("{ .reg .u64 t; cvta.to.shared.u64 t, %1; cvt.u32.u64 %0, t; }"
        : "=r"(a) : "l"(p));
    return a;
}
__device__ __forceinline__ void cp16(uint32_t dst, const void* src) {
    asm volatile("cp.async.cg.shared.global [%0], [%1], 16;" :: "r"(dst), "l"(src));
}
__device__ __forceinline__ void cp_commit() {
    asm volatile("cp.async.commit_group;" ::: "memory");
}
template <int N>
__device__ __forceinline__ void cp_wait() {
    asm volatile("cp.async.wait_group %0;" :: "n"(N) : "memory");
}
__device__ __forceinline__ void ldsm4(uint32_t* r, uint32_t addr) {
    asm volatile("ldmatrix.sync.aligned.m8n8.x4.shared.b16 {%0,%1,%2,%3}, [%4];"
                 : "=r"(r[0]), "=r"(r[1]), "=r"(r[2]), "=r"(r[3]) : "r"(addr));
}
__device__ __forceinline__ void ldsm4t(uint32_t* r, uint32_t addr) {
    asm volatile("ldmatrix.sync.aligned.m8n8.x4.trans.shared.b16 {%0,%1,%2,%3}, [%4];"
                 : "=r"(r[0]), "=r"(r[1]), "=r"(r[2]), "=r"(r[3]) : "r"(addr));
}
__device__ __forceinline__ void mma_fp(float* d, const uint32_t* a,
                                       const uint32_t* b) {
    asm volatile(
        "mma.sync.aligned.m16n8k16.row.col.f32.f16.f16.f32 "
        "{%0,%1,%2,%3}, {%4,%5,%6,%7}, {%8,%9}, {%0,%1,%2,%3};"
        : "+f"(d[0]), "+f"(d[1]), "+f"(d[2]), "+f"(d[3])
        : "r"(a[0]), "r"(a[1]), "r"(a[2]), "r"(a[3]), "r"(b[0]), "r"(b[1]));
}

// ---------------------------------------------------------------------------
// One fused fp32 -> fp16 conversion for all 7 tensors.
// ---------------------------------------------------------------------------
__device__ __forceinline__ void conv8(const float* __restrict__ s,
                                      __half* __restrict__ d, int i) {
    float4 a = *(const float4*)&s[i];
    float4 b = *(const float4*)&s[i + 4];
    __half2 h[4];
    h[0] = __floats2half2_rn(a.x, a.y);
    h[1] = __floats2half2_rn(a.z, a.w);
    h[2] = __floats2half2_rn(b.x, b.y);
    h[3] = __floats2half2_rn(b.z, b.w);
    *(uint4*)&d[i] = *(uint4*)h;
}

__global__ __launch_bounds__(256) void conv_all(
    const float* __restrict__ Q, const float* __restrict__ K,
    const float* __restrict__ V, const float* __restrict__ Wq,
    const float* __restrict__ Wk, const float* __restrict__ Wv,
    const float* __restrict__ Wo, __half* __restrict__ x3,
    __half* __restrict__ w3, __half* __restrict__ wo)
{
    const int bid = blockIdx.x;
    if (bid < 3 * BLKX) {
        const int seg = bid / BLKX;
        const int lb = bid - seg * BLKX;
        const float* src = (seg == 0) ? Q : (seg == 1) ? K : V;
        __half* dst = x3 + (size_t)seg * CNX;
        conv8(src, dst, lb * 2048 + threadIdx.x * 8);
    } else {
        const int r = bid - 3 * BLKX;
        const int seg = r / BLKW;
        const int lb = r - seg * BLKW;
        const float* src = (seg == 0) ? Wq : (seg == 1) ? Wk
                          : (seg == 2) ? Wv : Wo;
        __half* dst = (seg < 3) ? (w3 + (size_t)seg * CNW) : wo;
        conv8(src, dst, lb * 2048 + threadIdx.x * 8);
    }
}

// ---------------------------------------------------------------------------
// fp16 HMMA GEMM: O[z][M,N] = A[z][M,K] * W[z][N,K]^T + bias[z], fp32 accum.
// Tile 128x128x64, 8 warps (4M x 2N), 2-stage cp.async, ONE sync per iter.
// B-fragment register double-buffering hides LDS latency behind MMAs.
// ---------------------------------------------------------------------------
#define GBK 64
#define LDG_ 144                    // 128B data + 16B pad (conflict-free ldsm)
#define GTILE_B (128 * LDG_)        // 18432
#define GSTG_B (2 * GTILE_B)        // 36864
#define GNSTG 2

template <int NZ, int HOUT>
__global__ __launch_bounds__(256) void gemm_h(
    const __half* __restrict__ A0, const __half* __restrict__ W0,
    const float* __restrict__ bz0, const float* __restrict__ bz1,
    const float* __restrict__ bz2, void* __restrict__ Ov,
    int M, int N, int K)
{
    extern __shared__ __align__(128) char smem[];
    const int z = (NZ > 1) ? blockIdx.z : 0;
    const __half* A  = A0 + (size_t)z * M * K;
    const __half* Bm = W0 + (size_t)z * N * K;
    const float* bias = (z == 0) ? bz0 : (z == 1) ? bz1 : bz2;

    const int tid = threadIdx.x;
    const int wid = tid >> 5;
    const int lane = tid & 31;
    const int wm = (wid >> 1) * 32;
    const int wn = (wid & 1) * 64;
    const int m0 = blockIdx.y * 128;
    const int n0 = blockIdx.x * 128;

    const uint32_t sb = smem_u32(smem);
    const uint32_t arow = (uint32_t)(wm + (lane & 15)) * LDG_ + (lane >> 4) * 16;
    const uint32_t bbase = (uint32_t)(wn + (lane >> 4) * 8 + (lane & 7)) * LDG_ +
                           ((lane >> 3) & 1) * 16;

    float acc[2][8][4];
#pragma unroll
    for (int mt = 0; mt < 2; mt++)
#pragma unroll
        for (int nt = 0; nt < 8; nt++)
#pragma unroll
            for (int i = 0; i < 4; i++) acc[mt][nt][i] = 0.0f;

    const int NIT = K / GBK;   // 16

    auto load_stage = [&](int it, int slot) {
        const uint32_t stb = sb + slot * GSTG_B;
        const int k0 = it * GBK;
#pragma unroll
        for (int qq = 0; qq < 4; qq++) {
            int c = tid + qq * 256;          // 0..1023
            int row = c >> 3, ch = c & 7;    // 8 x 16B chunks per 128B row
            uint32_t so = (uint32_t)row * LDG_ + ch * 16;
            cp16(stb + so,           A  + (size_t)(m0 + row) * K + k0 + ch * 8);
            cp16(stb + GTILE_B + so, Bm + (size_t)(n0 + row) * K + k0 + ch * 8);
        }
        cp_commit();
    };

    load_stage(0, 0);

#pragma unroll 1
    for (int it = 0; it < NIT; it++) {
        const int slot = it & 1;
        cp_wait<0>();
        __syncthreads();   // data(it) ready; compute(it-1) on other slot done
        if (it + 1 < NIT) load_stage(it + 1, slot ^ 1);

        const uint32_t Ab = sb + slot * GSTG_B;
        const uint32_t Bb = Ab + GTILE_B;
#pragma unroll
        for (int ks = 0; ks < 4; ks++) {
            uint32_t a[2][4];
#pragma unroll
            for (int mt = 0; mt < 2; mt++)
                ldsm4(a[mt], Ab + arow + mt * (16 * LDG_) + ks * 32);
            uint32_t bf[2][4];
            ldsm4(bf[0], Bb + bbase + ks * 32);
#pragma unroll
            for (int np = 0; np < 4; np++) {
                if (np < 3)
                    ldsm4(bf[(np + 1) & 1],
                          Bb + bbase + (np + 1) * (16 * LDG_) + ks * 32);
                const uint32_t* b4 = bf[np & 1];
#pragma unroll
                for (int mt = 0; mt < 2; mt++) {
                    mma_fp(acc[mt][2 * np],     a[mt], b4);
                    mma_fp(acc[mt][2 * np + 1], a[mt], b4 + 2);
                }
            }
        }
    }

    __syncthreads();
    const int r0 = m0 + wm + (lane >> 2);
    const int c0 = n0 + wn + 2 * (lane & 3);
#pragma unroll
    for (int mt = 0; mt < 2; mt++) {
#pragma unroll
        for (int nt = 0; nt < 8; nt++) {
            int cc = c0 + nt * 8;
            float bx = __ldg(&bias[cc]);
            float by = __ldg(&bias[cc + 1]);
            int ra = r0 + mt * 16;
            if (HOUT) {
                __half2* O = (__half2*)Ov + (size_t)z * M * N / 2;
                O[((size_t)ra * N + cc) / 2] =
                    __floats2half2_rn(acc[mt][nt][0] + bx, acc[mt][nt][1] + by);
                O[((size_t)(ra + 8) * N + cc) / 2] =
                    __floats2half2_rn(acc[mt][nt][2] + bx, acc[mt][nt][3] + by);
            } else {
                float* O = (float*)Ov + (size_t)z * M * N;
                *(float2*)&O[(size_t)ra * N + cc] =
                    make_float2(acc[mt][nt][0] + bx, acc[mt][nt][1] + by);
                *(float2*)&O[(size_t)(ra + 8) * N + cc] =
                    make_float2(acc[mt][nt][2] + bx, acc[mt][nt][3] + by);
            }
        }
    }
}

// ---------------------------------------------------------------------------
// Flash attention, fp16 HMMA, fp32 online softmax, fp16 ctx output.
// B/V fragment double-buffering in np loops.
// ---------------------------------------------------------------------------
#define LDH 144
#define QS_B (128 * LDH)
#define KV_B (64 * LDH)

__global__ __launch_bounds__(256) void flash_attn_h(
    const __half* __restrict__ Qg, const __half* __restrict__ Kg,
    const __half* __restrict__ Vg, __half* __restrict__ Og)
{
    extern __shared__ __align__(128) char smem[];
    const int tid = threadIdx.x;
    const int wid = tid >> 5;
    const int lane = tid & 31;
    const int qt = blockIdx.x;
    const int h  = blockIdx.y;
    const int b  = blockIdx.z;

    const uint32_t sb = smem_u32(smem);
    const size_t hb = (size_t)b * Sz * Ez + (size_t)h * DKz;
    const __half* qg = Qg + hb + (size_t)qt * 128 * Ez;
    const __half* kg = Kg + hb;
    const __half* vg = Vg + hb;

#pragma unroll
    for (int i = 0; i < 4; i++) {
        int c = tid + i * 256;
        int row = c >> 3, ch = c & 7;
        cp16(sb + row * LDH + ch * 16, qg + (size_t)row * Ez + ch * 8);
    }
    cp_commit();

    auto load_kv = [&](int kt, int s) {
        const uint32_t kb = sb + QS_B + s * 2 * KV_B;
        const __half* kp = kg + (size_t)(kt * 64) * Ez;
        const __half* vp = vg + (size_t)(kt * 64) * Ez;
#pragma unroll
        for (int i = 0; i < 4; i++) {
            int c = tid + i * 256;
            int row = c >> 3, ch = c & 7;
            if (row < 64)
                cp16(kb + row * LDH + ch * 16, kp + (size_t)row * Ez + ch * 8);
            else
                cp16(kb + KV_B + (row - 64) * LDH + ch * 16,
                     vp + (size_t)(row - 64) * Ez + ch * 8);
        }
        cp_commit();
    };

    load_kv(0, 0);

    const uint32_t arow = (uint32_t)(wid * 16 + (lane & 15)) * LDH +
                          (lane >> 4) * 16;
    const uint32_t bbase = (uint32_t)((lane >> 4) * 8 + (lane & 7)) * LDH +
                           ((lane >> 3) & 1) * 16;
    const uint32_t vbase = (uint32_t)(lane & 15) * LDH + (lane >> 4) * 16;

    float o[8][4];
#pragma unroll
    for (int nt = 0; nt < 8; nt++)
#pragma unroll
        for (int i = 0; i < 4; i++) o[nt][i] = 0.0f;
    float m0 = -INFINITY, m1 = -INFINITY, l0 = 0.0f, l1 = 0.0f;

    const int NT = Sz / 64;
#pragma unroll 1
    for (int it = 0; it < NT; it++) {
        const int s = it & 1;
        const bool pf = (it + 1 < NT);
        if (pf) load_kv(it + 1, s ^ 1);
        if (pf) cp_wait<1>(); else cp_wait<0>();
        __syncthreads();

        const uint32_t Kb = sb + QS_B + s * 2 * KV_B;
        const uint32_t Vb = Kb + KV_B;

        float sv[8][4];
#pragma unroll
        for (int nt = 0; nt < 8; nt++)
#pragma unroll
            for (int i = 0; i < 4; i++) sv[nt][i] = 0.0f;
#pragma unroll
        for (int ks = 0; ks < 4; ks++) {
            uint32_t qa[4];
            ldsm4(qa, sb + arow + ks * 32);
            uint32_t bf[2][4];
            ldsm4(bf[0], Kb + bbase + ks * 32);
#pragma unroll
            for (int np = 0; np < 4; np++) {
                if (np < 3)
                    ldsm4(bf[(np + 1) & 1],
                          Kb + bbase + (np + 1) * (16 * LDH) + ks * 32);
                const uint32_t* b4 = bf[np & 1];
                mma_fp(sv[2 * np],     qa, b4);
                mma_fp(sv[2 * np + 1], qa, b4 + 2);
            }
        }

        float mx0 = -INFINITY, mx1 = -INFINITY;
#pragma unroll
        for (int nt = 0; nt < 8; nt++) {
            sv[nt][0] *= 0.125f; sv[nt][1] *= 0.125f;
            sv[nt][2] *= 0.125f; sv[nt][3] *= 0.125f;
            mx0 = fmaxf(mx0, fmaxf(sv[nt][0], sv[nt][1]));
            mx1 = fmaxf(mx1, fmaxf(sv[nt][2], sv[nt][3]));
        }
        mx0 = fmaxf(mx0, __shfl_xor_sync(0xffffffffu, mx0, 1));
        mx0 = fmaxf(mx0, __shfl_xor_sync(0xffffffffu, mx0, 2));
        mx1 = fmaxf(mx1, __shfl_xor_sync(0xffffffffu, mx1, 1));
        mx1 = fmaxf(mx1, __shfl_xor_sync(0xffffffffu, mx1, 2));
        float mn0 = fmaxf(m0, mx0), mn1 = fmaxf(m1, mx1);
        float cr0 = __expf(m0 - mn0), cr1 = __expf(m1 - mn1);
        float sum0 = 0.0f, sum1 = 0.0f;
#pragma unroll
        for (int nt = 0; nt < 8; nt++) {
            sv[nt][0] = __expf(sv[nt][0] - mn0);
            sv[nt][1] = __expf(sv[nt][1] - mn0);
            sv[nt][2] = __expf(sv[nt][2] - mn1);
            sv[nt][3] = __expf(sv[nt][3] - mn1);
            sum0 += sv[nt][0] + sv[nt][1];
            sum1 += sv[nt][2] + sv[nt][3];
        }
        sum0 += __shfl_xor_sync(0xffffffffu, sum0, 1);
        sum0 += __shfl_xor_sync(0xffffffffu, sum0, 2);
        sum1 += __shfl_xor_sync(0xffffffffu, sum1, 1);
        sum1 += __shfl_xor_sync(0xffffffffu, sum1, 2);
        l0 = l0 * cr0 + sum0;
        l1 = l1 * cr1 + sum1;
        m0 = mn0; m1 = mn1;
#pragma unroll
        for (int nt = 0; nt < 8; nt++) {
            o[nt][0] *= cr0; o[nt][1] *= cr0;
            o[nt][2] *= cr1; o[nt][3] *= cr1;
        }

#pragma unroll
        for (int ks = 0; ks < 4; ks++) {
            uint32_t pa[4];
            __half2 h0h = __floats2half2_rn(sv[2 * ks][0], sv[2 * ks][1]);
            __half2 h1h = __floats2half2_rn(sv[2 * ks][2], sv[2 * ks][3]);
            __half2 h2h = __floats2half2_rn(sv[2 * ks + 1][0], sv[2 * ks + 1][1]);
            __half2 h3h = __floats2half2_rn(sv[2 * ks + 1][2], sv[2 * ks + 1][3]);
            pa[0] = *(uint32_t*)&h0h; pa[1] = *(uint32_t*)&h1h;
            pa[2] = *(uint32_t*)&h2h; pa[3] = *(uint32_t*)&h3h;
            uint32_t vf[2][4];
            ldsm4t(vf[0], Vb + vbase + ks * (16 * LDH));
#pragma unroll
            for (int np = 0; np < 4; np++) {
                if (np < 3)
                    ldsm4t(vf[(np + 1) & 1],
                           Vb + vbase + ks * (16 * LDH) + (np + 1) * 32);
                const uint32_t* v4 = vf[np & 1];
                mma_fp(o[2 * np],     pa, v4);
                mma_fp(o[2 * np + 1], pa, v4 + 2);
            }
        }
        __syncthreads();
    }

    const float i0 = 1.0f / l0, i1 = 1.0f / l1;
    const int gr0 = qt * 128 + wid * 16 + (lane >> 2);
    const int cbase = h * 64 + 2 * (lane & 3);
#pragma unroll
    for (int nt = 0; nt < 8; nt++) {
        int cc = cbase + nt * 8;
        *(__half2*)&Og[((size_t)(b * Sz + gr0)) * Ez + cc] =
            __floats2half2_rn(o[nt][0] * i0, o[nt][1] * i0);
        *(__half2*)&Og[((size_t)(b * Sz + gr0 + 8)) * Ez + cc] =
            __floats2half2_rn(o[nt][2] * i1, o[nt][3] * i1);
    }
}

// ---------------------------------------------------------------------------
extern "C" void kernel_launch(void* const* d_in, const int* in_sizes, int n_in,
                              void* d_out, int out_size)
{
    const float* Q  = (const float*)d_in[0];
    const float* K  = (const float*)d_in[1];
    const float* V  = (const float*)d_in[2];
    const float* Wq = (const float*)d_in[3];
    const float* bq = (const float*)d_in[4];
    const float* Wk = (const float*)d_in[5];
    const float* bk = (const float*)d_in[6];
    const float* Wv = (const float*)d_in[7];
    const float* bv = (const float*)d_in[8];
    const float* Wo = (const float*)d_in[9];
    const float* bo = (const float*)d_in[10];
    float* out = (float*)d_out;

    __half *x3, *w3, *wo, *qkv, *ctxh;
    cudaGetSymbolAddress((void**)&x3,   g_x3);
    cudaGetSymbolAddress((void**)&w3,   g_w3);
    cudaGetSymbolAddress((void**)&wo,   g_wo);
    cudaGetSymbolAddress((void**)&qkv,  g_qkv);
    cudaGetSymbolAddress((void**)&ctxh, g_ctxh);

    cudaFuncSetAttribute(flash_attn_h,
                         cudaFuncAttributeMaxDynamicSharedMemorySize,
                         QS_B + 4 * KV_B);
    cudaFuncSetAttribute(gemm_h<3, 1>,
                         cudaFuncAttributeMaxDynamicSharedMemorySize,
                         GNSTG * GSTG_B);
    cudaFuncSetAttribute(gemm_h<1, 0>,
                         cudaFuncAttributeMaxDynamicSharedMemorySize,
                         GNSTG * GSTG_B);

    const int M = Bz * Sz;

    conv_all<<<3 * BLKX + 4 * BLKW, 256>>>(Q, K, V, Wq, Wk, Wv, Wo, x3, w3, wo);

    gemm_h<3, 1><<<dim3(Ez / 128, M / 128, 3), 256, GNSTG * GSTG_B>>>(
        x3, w3, bq, bk, bv, qkv, M, Ez, Ez);

    flash_attn_h<<<dim3(Sz / 128, Hz, Bz), 256, QS_B + 4 * KV_B>>>(
        qkv, qkv + (size_t)CNX, qkv + 2 * (size_t)CNX, ctxh);

    gemm_h<1, 0><<<dim3(Ez / 128, M / 128, 1), 256, GNSTG * GSTG_B>>>(
        ctxh, wo, bo, bo, bo, out, M, Ez, Ez);
}

// round 8
// speedup vs baseline: 7.1105x; 1.0036x over previous
#include <cuda_runtime.h>
#include <cuda_fp16.h>
#include <math.h>
#include <stdint.h>

#define Bz 4
#define Sz 2048
#define Ez 1024
#define Hz 16
#define DKz 64

#define CNX (Bz * Sz * Ez)   // 8388608
#define CNW (Ez * Ez)        // 1048576
#define BLKX (CNX / 2048)    // 4096
#define BLKW (CNW / 2048)    // 512

// ---------------------------------------------------------------------------
// Scratch (no allocs allowed)
// ---------------------------------------------------------------------------
__device__ __half g_x3[3 * CNX];    // converted Q,K,V inputs (contiguous)
__device__ __half g_w3[3 * CNW];    // converted Wq(*1/8),Wk,Wv (contiguous)
__device__ __half g_wo[CNW];        // converted Wo
__device__ __half g_qkv[3 * CNX];   // projected q(*1/8),k,v (contiguous)
__device__ __half g_ctxh[CNX];      // attention context

// ---------------------------------------------------------------------------
// Base-target PTX helpers (NO tcgen05 — harness compiles for sm_103 base)
// ---------------------------------------------------------------------------
__device__ __forceinline__ uint32_t smem_u32(const void* p) {
    uint32_t a;
    asm("{ .reg .u64 t; cvta.to.shared.u64 t, %1; cvt.u32.u64 %0, t; }"
        : "=r"(a) : "l"(p));
    return a;
}
__device__ __forceinline__ void cp16(uint32_t dst, const void* src) {
    asm volatile("cp.async.cg.shared.global [%0], [%1], 16;" :: "r"(dst), "l"(src));
}
__device__ __forceinline__ void cp_commit() {
    asm volatile("cp.async.commit_group;" ::: "memory");
}
template <int N>
__device__ __forceinline__ void cp_wait() {
    asm volatile("cp.async.wait_group %0;" :: "n"(N) : "memory");
}
__device__ __forceinline__ void ldsm4(uint32_t* r, uint32_t addr) {
    asm volatile("ldmatrix.sync.aligned.m8n8.x4.shared.b16 {%0,%1,%2,%3}, [%4];"
                 : "=r"(r[0]), "=r"(r[1]), "=r"(r[2]), "=r"(r[3]) : "r"(addr));
}
__device__ __forceinline__ void ldsm4t(uint32_t* r, uint32_t addr) {
    asm volatile("ldmatrix.sync.aligned.m8n8.x4.trans.shared.b16 {%0,%1,%2,%3}, [%4];"
                 : "=r"(r[0]), "=r"(r[1]), "=r"(r[2]), "=r"(r[3]) : "r"(addr));
}
__device__ __forceinline__ void mma_fp(float* d, const uint32_t* a,
                                       const uint32_t* b) {
    asm volatile(
        "mma.sync.aligned.m16n8k16.row.col.f32.f16.f16.f32 "
        "{%0,%1,%2,%3}, {%4,%5,%6,%7}, {%8,%9}, {%0,%1,%2,%3};"
        : "+f"(d[0]), "+f"(d[1]), "+f"(d[2]), "+f"(d[3])
        : "r"(a[0]), "r"(a[1]), "r"(a[2]), "r"(a[3]), "r"(b[0]), "r"(b[1]));
}

// ---------------------------------------------------------------------------
// One fused fp32 -> fp16 conversion for all 7 tensors.
// Wq is pre-scaled by 1/8 (folds attention 1/sqrt(dk) into projection).
// ---------------------------------------------------------------------------
__device__ __forceinline__ void conv8(const float* __restrict__ s,
                                      __half* __restrict__ d, int i, float sc) {
    float4 a = *(const float4*)&s[i];
    float4 b = *(const float4*)&s[i + 4];
    __half2 h[4];
    h[0] = __floats2half2_rn(a.x * sc, a.y * sc);
    h[1] = __floats2half2_rn(a.z * sc, a.w * sc);
    h[2] = __floats2half2_rn(b.x * sc, b.y * sc);
    h[3] = __floats2half2_rn(b.z * sc, b.w * sc);
    *(uint4*)&d[i] = *(uint4*)h;
}

__global__ __launch_bounds__(256) void conv_all(
    const float* __restrict__ Q, const float* __restrict__ K,
    const float* __restrict__ V, const float* __restrict__ Wq,
    const float* __restrict__ Wk, const float* __restrict__ Wv,
    const float* __restrict__ Wo, __half* __restrict__ x3,
    __half* __restrict__ w3, __half* __restrict__ wo)
{
    const int bid = blockIdx.x;
    if (bid < 3 * BLKX) {
        const int seg = bid / BLKX;
        const int lb = bid - seg * BLKX;
        const float* src = (seg == 0) ? Q : (seg == 1) ? K : V;
        __half* dst = x3 + (size_t)seg * CNX;
        conv8(src, dst, lb * 2048 + threadIdx.x * 8, 1.0f);
    } else {
        const int r = bid - 3 * BLKX;
        const int seg = r / BLKW;
        const int lb = r - seg * BLKW;
        const float* src = (seg == 0) ? Wq : (seg == 1) ? Wk
                          : (seg == 2) ? Wv : Wo;
        __half* dst = (seg < 3) ? (w3 + (size_t)seg * CNW) : wo;
        conv8(src, dst, lb * 2048 + threadIdx.x * 8,
              (seg == 0) ? 0.125f : 1.0f);
    }
}

// ---------------------------------------------------------------------------
// fp16 HMMA GEMM: O[z][M,N] = A[z][M,K] * W[z][N,K]^T + bias[z], fp32 accum.
// Tile 128x128x64, 8 warps (4M x 2N), 3-stage cp.async, ONE sync per iter.
// z==0 (Q) bias scaled by 1/8 to match pre-scaled Wq.
// ---------------------------------------------------------------------------
#define GBK 64
#define LDG_ 144
#define GTILE_B (128 * LDG_)        // 18432
#define GSTG_B (2 * GTILE_B)        // 36864
#define GNSTG 3

template <int NZ, int HOUT>
__global__ __launch_bounds__(256) void gemm_h(
    const __half* __restrict__ A0, const __half* __restrict__ W0,
    const float* __restrict__ bz0, const float* __restrict__ bz1,
    const float* __restrict__ bz2, void* __restrict__ Ov,
    int M, int N, int K)
{
    extern __shared__ __align__(128) char smem[];
    const int z = (NZ > 1) ? blockIdx.z : 0;
    const __half* A  = A0 + (size_t)z * M * K;
    const __half* Bm = W0 + (size_t)z * N * K;
    const float* bias = (z == 0) ? bz0 : (z == 1) ? bz1 : bz2;
    const float bsc = (NZ > 1 && z == 0) ? 0.125f : 1.0f;

    const int tid = threadIdx.x;
    const int wid = tid >> 5;
    const int lane = tid & 31;
    const int wm = (wid >> 1) * 32;
    const int wn = (wid & 1) * 64;
    const int m0 = blockIdx.y * 128;
    const int n0 = blockIdx.x * 128;

    const uint32_t sb = smem_u32(smem);
    const uint32_t arow = (uint32_t)(wm + (lane & 15)) * LDG_ + (lane >> 4) * 16;
    const uint32_t bbase = (uint32_t)(wn + (lane >> 4) * 8 + (lane & 7)) * LDG_ +
                           ((lane >> 3) & 1) * 16;

    float acc[2][8][4];
#pragma unroll
    for (int mt = 0; mt < 2; mt++)
#pragma unroll
        for (int nt = 0; nt < 8; nt++)
#pragma unroll
            for (int i = 0; i < 4; i++) acc[mt][nt][i] = 0.0f;

    const int NIT = K / GBK;   // 16

    auto load_stage = [&](int it, int slot) {
        const uint32_t stb = sb + slot * GSTG_B;
        const int k0 = it * GBK;
#pragma unroll
        for (int qq = 0; qq < 4; qq++) {
            int c = tid + qq * 256;
            int row = c >> 3, ch = c & 7;
            uint32_t so = (uint32_t)row * LDG_ + ch * 16;
            cp16(stb + so,           A  + (size_t)(m0 + row) * K + k0 + ch * 8);
            cp16(stb + GTILE_B + so, Bm + (size_t)(n0 + row) * K + k0 + ch * 8);
        }
        cp_commit();
    };

    load_stage(0, 0);
    load_stage(1, 1);

#pragma unroll 1
    for (int it = 0; it < NIT; it++) {
        const int slot = it % GNSTG;
        if (it < NIT - 1) cp_wait<1>(); else cp_wait<0>();
        __syncthreads();   // data(it) ready; slot (it-1)%3 fully consumed
        if (it + 2 < NIT) load_stage(it + 2, (it + 2) % GNSTG);

        const uint32_t Ab = sb + slot * GSTG_B;
        const uint32_t Bb = Ab + GTILE_B;
#pragma unroll
        for (int ks = 0; ks < 4; ks++) {
            uint32_t a[2][4];
#pragma unroll
            for (int mt = 0; mt < 2; mt++)
                ldsm4(a[mt], Ab + arow + mt * (16 * LDG_) + ks * 32);
            uint32_t bf[2][4];
            ldsm4(bf[0], Bb + bbase + ks * 32);
#pragma unroll
            for (int np = 0; np < 4; np++) {
                if (np < 3)
                    ldsm4(bf[(np + 1) & 1],
                          Bb + bbase + (np + 1) * (16 * LDG_) + ks * 32);
                const uint32_t* b4 = bf[np & 1];
#pragma unroll
                for (int mt = 0; mt < 2; mt++) {
                    mma_fp(acc[mt][2 * np],     a[mt], b4);
                    mma_fp(acc[mt][2 * np + 1], a[mt], b4 + 2);
                }
            }
        }
    }

    __syncthreads();
    const int r0 = m0 + wm + (lane >> 2);
    const int c0 = n0 + wn + 2 * (lane & 3);
#pragma unroll
    for (int mt = 0; mt < 2; mt++) {
#pragma unroll
        for (int nt = 0; nt < 8; nt++) {
            int cc = c0 + nt * 8;
            float bx = __ldg(&bias[cc]) * bsc;
            float by = __ldg(&bias[cc + 1]) * bsc;
            int ra = r0 + mt * 16;
            if (HOUT) {
                __half2* O = (__half2*)Ov + (size_t)z * M * N / 2;
                O[((size_t)ra * N + cc) / 2] =
                    __floats2half2_rn(acc[mt][nt][0] + bx, acc[mt][nt][1] + by);
                O[((size_t)(ra + 8) * N + cc) / 2] =
                    __floats2half2_rn(acc[mt][nt][2] + bx, acc[mt][nt][3] + by);
            } else {
                float* O = (float*)Ov + (size_t)z * M * N;
                *(float2*)&O[(size_t)ra * N + cc] =
                    make_float2(acc[mt][nt][0] + bx, acc[mt][nt][1] + by);
                *(float2*)&O[(size_t)(ra + 8) * N + cc] =
                    make_float2(acc[mt][nt][2] + bx, acc[mt][nt][3] + by);
            }
        }
    }
}

// ---------------------------------------------------------------------------
// Flash attention, fp16 HMMA, fp32 online softmax, fp16 ctx output.
// Q pre-scaled by 1/8 (no scale pass). 3-stage KV pipeline, 1 sync/iter.
// exp (MUFU) interleaved with PV tensor work per 16-key chunk.
// ---------------------------------------------------------------------------
#define LDH 144
#define QS_B (128 * LDH)
#define KV_B (64 * LDH)
#define KVSTG_B (2 * KV_B)

__global__ __launch_bounds__(256) void flash_attn_h(
    const __half* __restrict__ Qg, const __half* __restrict__ Kg,
    const __half* __restrict__ Vg, __half* __restrict__ Og)
{
    extern __shared__ __align__(128) char smem[];
    const int tid = threadIdx.x;
    const int wid = tid >> 5;
    const int lane = tid & 31;
    const int qt = blockIdx.x;
    const int h  = blockIdx.y;
    const int b  = blockIdx.z;

    const uint32_t sb = smem_u32(smem);
    const size_t hb = (size_t)b * Sz * Ez + (size_t)h * DKz;
    const __half* qg = Qg + hb + (size_t)qt * 128 * Ez;
    const __half* kg = Kg + hb;
    const __half* vg = Vg + hb;

#pragma unroll
    for (int i = 0; i < 4; i++) {
        int c = tid + i * 256;
        int row = c >> 3, ch = c & 7;
        cp16(sb + row * LDH + ch * 16, qg + (size_t)row * Ez + ch * 8);
    }
    cp_commit();

    auto load_kv = [&](int kt, int s) {
        const uint32_t kb = sb + QS_B + s * KVSTG_B;
        const __half* kp = kg + (size_t)(kt * 64) * Ez;
        const __half* vp = vg + (size_t)(kt * 64) * Ez;
#pragma unroll
        for (int i = 0; i < 4; i++) {
            int c = tid + i * 256;
            int row = c >> 3, ch = c & 7;
            if (row < 64)
                cp16(kb + row * LDH + ch * 16, kp + (size_t)row * Ez + ch * 8);
            else
                cp16(kb + KV_B + (row - 64) * LDH + ch * 16,
                     vp + (size_t)(row - 64) * Ez + ch * 8);
        }
        cp_commit();
    };

    load_kv(0, 0);
    load_kv(1, 1);

    const uint32_t arow = (uint32_t)(wid * 16 + (lane & 15)) * LDH +
                          (lane >> 4) * 16;
    const uint32_t bbase = (uint32_t)((lane >> 4) * 8 + (lane & 7)) * LDH +
                           ((lane >> 3) & 1) * 16;
    const uint32_t vbase = (uint32_t)(lane & 15) * LDH + (lane >> 4) * 16;

    float o[8][4];
#pragma unroll
    for (int nt = 0; nt < 8; nt++)
#pragma unroll
        for (int i = 0; i < 4; i++) o[nt][i] = 0.0f;
    float m0 = -INFINITY, m1 = -INFINITY, l0 = 0.0f, l1 = 0.0f;

    const int NT = Sz / 64;   // 32
#pragma unroll 1
    for (int it = 0; it < NT; it++) {
        const int slot = it % 3;
        if (it < NT - 1) cp_wait<1>(); else cp_wait<0>();
        __syncthreads();   // KV(it) ready; slot (it-1)%3 consumed by all warps
        if (it + 2 < NT) load_kv(it + 2, (it + 2) % 3);

        const uint32_t Kb = sb + QS_B + slot * KVSTG_B;
        const uint32_t Vb = Kb + KV_B;

        // S = Q K^T  (Q pre-scaled by 1/8)
        float sv[8][4];
#pragma unroll
        for (int nt = 0; nt < 8; nt++)
#pragma unroll
            for (int i = 0; i < 4; i++) sv[nt][i] = 0.0f;
#pragma unroll
        for (int ks = 0; ks < 4; ks++) {
            uint32_t qa[4];
            ldsm4(qa, sb + arow + ks * 32);
            uint32_t bf[2][4];
            ldsm4(bf[0], Kb + bbase + ks * 32);
#pragma unroll
            for (int np = 0; np < 4; np++) {
                if (np < 3)
                    ldsm4(bf[(np + 1) & 1],
                          Kb + bbase + (np + 1) * (16 * LDH) + ks * 32);
                const uint32_t* b4 = bf[np & 1];
                mma_fp(sv[2 * np],     qa, b4);
                mma_fp(sv[2 * np + 1], qa, b4 + 2);
            }
        }

        // row max + rescale state
        float mx0 = -INFINITY, mx1 = -INFINITY;
#pragma unroll
        for (int nt = 0; nt < 8; nt++) {
            mx0 = fmaxf(mx0, fmaxf(sv[nt][0], sv[nt][1]));
            mx1 = fmaxf(mx1, fmaxf(sv[nt][2], sv[nt][3]));
        }
        mx0 = fmaxf(mx0, __shfl_xor_sync(0xffffffffu, mx0, 1));
        mx0 = fmaxf(mx0, __shfl_xor_sync(0xffffffffu, mx0, 2));
        mx1 = fmaxf(mx1, __shfl_xor_sync(0xffffffffu, mx1, 1));
        mx1 = fmaxf(mx1, __shfl_xor_sync(0xffffffffu, mx1, 2));
        float mn0 = fmaxf(m0, mx0), mn1 = fmaxf(m1, mx1);
        float cr0 = __expf(m0 - mn0), cr1 = __expf(m1 - mn1);
#pragma unroll
        for (int nt = 0; nt < 8; nt++) {
            o[nt][0] *= cr0; o[nt][1] *= cr0;
            o[nt][2] *= cr1; o[nt][3] *= cr1;
        }

        // per-16-key chunk: exp (MUFU) interleaved with V ldsm + PV MMA
        float sum0 = 0.0f, sum1 = 0.0f;
#pragma unroll
        for (int ks = 0; ks < 4; ks++) {
            float e00 = __expf(sv[2 * ks][0] - mn0);
            float e01 = __expf(sv[2 * ks][1] - mn0);
            float e02 = __expf(sv[2 * ks][2] - mn1);
            float e03 = __expf(sv[2 * ks][3] - mn1);
            float e10 = __expf(sv[2 * ks + 1][0] - mn0);
            float e11 = __expf(sv[2 * ks + 1][1] - mn0);
            float e12 = __expf(sv[2 * ks + 1][2] - mn1);
            float e13 = __expf(sv[2 * ks + 1][3] - mn1);
            sum0 += e00 + e01 + e10 + e11;
            sum1 += e02 + e03 + e12 + e13;
            uint32_t pa[4];
            __half2 h0h = __floats2half2_rn(e00, e01);
            __half2 h1h = __floats2half2_rn(e02, e03);
            __half2 h2h = __floats2half2_rn(e10, e11);
            __half2 h3h = __floats2half2_rn(e12, e13);
            pa[0] = *(uint32_t*)&h0h; pa[1] = *(uint32_t*)&h1h;
            pa[2] = *(uint32_t*)&h2h; pa[3] = *(uint32_t*)&h3h;
            uint32_t vf[2][4];
            ldsm4t(vf[0], Vb + vbase + ks * (16 * LDH));
#pragma unroll
            for (int np = 0; np < 4; np++) {
                if (np < 3)
                    ldsm4t(vf[(np + 1) & 1],
                           Vb + vbase + ks * (16 * LDH) + (np + 1) * 32);
                const uint32_t* v4 = vf[np & 1];
                mma_fp(o[2 * np],     pa, v4);
                mma_fp(o[2 * np + 1], pa, v4 + 2);
            }
        }
        sum0 += __shfl_xor_sync(0xffffffffu, sum0, 1);
        sum0 += __shfl_xor_sync(0xffffffffu, sum0, 2);
        sum1 += __shfl_xor_sync(0xffffffffu, sum1, 1);
        sum1 += __shfl_xor_sync(0xffffffffu, sum1, 2);
        l0 = l0 * cr0 + sum0;
        l1 = l1 * cr1 + sum1;
        m0 = mn0; m1 = mn1;
    }

    const float i0 = 1.0f / l0, i1 = 1.0f / l1;
    const int gr0 = qt * 128 + wid * 16 + (lane >> 2);
    const int cbase = h * 64 + 2 * (lane & 3);
#pragma unroll
    for (int nt = 0; nt < 8; nt++) {
        int cc = cbase + nt * 8;
        *(__half2*)&Og[((size_t)(b * Sz + gr0)) * Ez + cc] =
            __floats2half2_rn(o[nt][0] * i0, o[nt][1] * i0);
        *(__half2*)&Og[((size_t)(b * Sz + gr0 + 8)) * Ez + cc] =
            __floats2half2_rn(o[nt][2] * i1, o[nt][3] * i1);
    }
}

// ---------------------------------------------------------------------------
extern "C" void kernel_launch(void* const* d_in, const int* in_sizes, int n_in,
                              void* d_out, int out_size)
{
    const float* Q  = (const float*)d_in[0];
    const float* K  = (const float*)d_in[1];
    const float* V  = (const float*)d_in[2];
    const float* Wq = (const float*)d_in[3];
    const float* bq = (const float*)d_in[4];
    const float* Wk = (const float*)d_in[5];
    const float* bk = (const float*)d_in[6];
    const float* Wv = (const float*)d_in[7];
    const float* bv = (const float*)d_in[8];
    const float* Wo = (const float*)d_in[9];
    const float* bo = (const float*)d_in[10];
    float* out = (float*)d_out;

    __half *x3, *w3, *wo, *qkv, *ctxh;
    cudaGetSymbolAddress((void**)&x3,   g_x3);
    cudaGetSymbolAddress((void**)&w3,   g_w3);
    cudaGetSymbolAddress((void**)&wo,   g_wo);
    cudaGetSymbolAddress((void**)&qkv,  g_qkv);
    cudaGetSymbolAddress((void**)&ctxh, g_ctxh);

    cudaFuncSetAttribute(flash_attn_h,
                         cudaFuncAttributeMaxDynamicSharedMemorySize,
                         QS_B + 3 * KVSTG_B);
    cudaFuncSetAttribute(gemm_h<3, 1>,
                         cudaFuncAttributeMaxDynamicSharedMemorySize,
                         GNSTG * GSTG_B);
    cudaFuncSetAttribute(gemm_h<1, 0>,
                         cudaFuncAttributeMaxDynamicSharedMemorySize,
                         GNSTG * GSTG_B);

    const int M = Bz * Sz;

    conv_all<<<3 * BLKX + 4 * BLKW, 256>>>(Q, K, V, Wq, Wk, Wv, Wo, x3, w3, wo);

    gemm_h<3, 1><<<dim3(Ez / 128, M / 128, 3), 256, GNSTG * GSTG_B>>>(
        x3, w3, bq, bk, bv, qkv, M, Ez, Ez);

    flash_attn_h<<<dim3(Sz / 128, Hz, Bz), 256, QS_B + 3 * KVSTG_B>>>(
        qkv, qkv + (size_t)CNX, qkv + 2 * (size_t)CNX, ctxh);

    gemm_h<1, 0><<<dim3(Ez / 128, M / 128, 1), 256, GNSTG * GSTG_B>>>(
        ctxh, wo, bo, bo, bo, out, M, Ez, Ez);
}